// round 11
// baseline (speedup 1.0000x reference)
#include <cuda_runtime.h>
#include <cuda_bf16.h>
#include <cstdint>

// Fixed problem shapes
#define SIGMA   16
#define PATCH   33
#define HW      256
#define NPATCH  1024
#define C1      32
#define C1H     31
#define C2      64
#define C2H     15
#define OUTF    128

// conv1 fp32 patch staging (padded rows)
#define PROW    36
#define PPL     (PATCH * PROW)          // 1188 floats / channel

// smem byte layout
#define BUF0_OFF   0
#define QROW       80
#define BUF0_BYTES (1024 * QROW)        // 81920
#define W2S_OFF    81920                // 9*64 rows x 80B = 46080
#define PATCH_OFF  128000               // 3*1188*4 = 14256 (pad 14336)
#define W1B_OFF    142336               // 32 rows x 80B = 2560
#define B1S_OFF    144896               // 32*4
#define B2S_OFF    145024               // 64*4
#define PART_OFF   145280               // 16*64*4 = 4096 (aliased: qoff table)
#define SMEM_BYTES 149504

__device__ float g_h[2 * NPATCH * C2];
__device__ float g_pairsum[NPATCH];
__device__ unsigned int g_done_ctr = 0;
// pre-converted weight images (bf16, 80B rows) — written by prep_kernel
__device__ uint4 g_w2s4[2880];          // 46080 B
__device__ uint4 g_w1b4[160];           // 2560 B

__device__ __forceinline__ uint32_t smem_u32(const void* p) {
    uint32_t a;
    asm("{ .reg .u64 t; cvta.to.shared.u64 t, %1; cvt.u32.u64 %0, t; }" : "=r"(a) : "l"(p));
    return a;
}

__device__ __forceinline__ void ldsm_x4(uint32_t addr, uint32_t& r0, uint32_t& r1,
                                        uint32_t& r2, uint32_t& r3) {
    asm volatile("ldmatrix.sync.aligned.m8n8.x4.shared.b16 {%0,%1,%2,%3}, [%4];"
                 : "=r"(r0), "=r"(r1), "=r"(r2), "=r"(r3) : "r"(addr));
}

__device__ __forceinline__ void mma16816(float* d, uint32_t a0, uint32_t a1,
                                         uint32_t a2, uint32_t a3,
                                         uint32_t b0, uint32_t b1) {
    asm volatile("mma.sync.aligned.m16n8k16.row.col.f32.bf16.bf16.f32 "
                 "{%0,%1,%2,%3}, {%4,%5,%6,%7}, {%8,%9}, {%0,%1,%2,%3};"
                 : "+f"(d[0]), "+f"(d[1]), "+f"(d[2]), "+f"(d[3])
                 : "r"(a0), "r"(a1), "r"(a2), "r"(a3), "r"(b0), "r"(b1));
}

__device__ __forceinline__ uint32_t bfpack(float lo, float hi) {
    __nv_bfloat162 v = __floats2bfloat162_rn(lo, hi);
    return *(uint32_t*)&v;
}

__device__ __forceinline__ void cp_async16(uint32_t dst, const void* src) {
    asm volatile("cp.async.ca.shared.global [%0], [%1], 16;" :: "r"(dst), "l"(src));
}

// quadrant smem row byte-offset for conv1-output pixel m = y*31+x
__device__ __forceinline__ uint32_t quad_row_off(int m) {
    int y = m / 31;
    int x = m - 31 * y;
    int row = ((((y & 1) << 1) | (x & 1)) << 8) + ((y >> 1) << 4) + (x >> 1);
    return (uint32_t)row * QROW;
}

// pack 27-tap fp32 vector -> 64B bf16 A row (stride 80B)
__device__ __forceinline__ void store_a_row(char* smc, int mm, const float* v) {
    uint32_t r[16];
    #pragma unroll
    for (int i = 0; i < 13; i++) r[i] = bfpack(v[2 * i], v[2 * i + 1]);
    r[13] = bfpack(v[26], 0.f);
    r[14] = 0u; r[15] = 0u;
    uint4* dst = (uint4*)(smc + BUF0_OFF + mm * QROW);
    dst[0] = make_uint4(r[0], r[1], r[2], r[3]);
    dst[1] = make_uint4(r[4], r[5], r[6], r[7]);
    dst[2] = make_uint4(r[8], r[9], r[10], r[11]);
    dst[3] = make_uint4(r[12], r[13], r[14], r[15]);
}

// ---------------------------------------------------------------------------
// Prep kernel: convert w1/w2 into bf16 smem-image layouts once (32 blocks).
// ---------------------------------------------------------------------------
__global__ void __launch_bounds__(512)
prep_kernel(const float* __restrict__ w1, const float* __restrict__ w2)
{
    const int i = blockIdx.x * 512 + threadIdx.x;   // 16384 threads total
    if (i < 11520) {                                 // w2s u32 image
        int row = i / 20, c = i - row * 20;
        uint32_t val = 0u;
        if (c < 16) {
            int tap = row >> 6, oc = row & 63;
            int ky = tap / 3, kx = tap - 3 * ky;
            const float* ws = w2 + ((size_t)(oc * C1 + 2 * c) * 3 + ky) * 3 + kx;
            val = bfpack(ws[0], ws[9]);
        }
        ((uint32_t*)g_w2s4)[i] = val;
    }
    if (i < 640) {                                   // w1b u32 image
        int oc = i / 20, c = i - oc * 20;
        uint32_t val = 0u;
        if (c < 16) {
            float lo = (2 * c     < 27) ? w1[oc * 27 + 2 * c]     : 0.f;
            float hi = (2 * c + 1 < 27) ? w1[oc * 27 + 2 * c + 1] : 0.f;
            val = bfpack(lo, hi);
        }
        ((uint32_t*)g_w1b4)[i] = val;
    }
}

// ---------------------------------------------------------------------------
// Kernel A: per-patch CNN up to GAP. One block/patch (2048 x 512).
// conv1: im2col + mma.sync bf16.  conv2: 9 shifted GEMMs, mma.sync bf16,
//        m32n32 warp tiles (warp = (mg, ng)).
// ---------------------------------------------------------------------------
__global__ void __launch_bounds__(512, 1)
patch_cnn_kernel(const float* __restrict__ img_g, const float* __restrict__ img_s,
                 const float* __restrict__ kp_g,  const float* __restrict__ kp_s,
                 const float* __restrict__ b1,    const float* __restrict__ b2)
{
    extern __shared__ char smc[];
    float* patch = (float*)(smc + PATCH_OFF);
    float* b1s   = (float*)(smc + B1S_OFF);
    float* b2s   = (float*)(smc + B2S_OFF);
    float* part  = (float*)(smc + PART_OFF);
    uint32_t* qofft = (uint32_t*)(smc + PART_OFF);   // alias: dead before epilogue
    const uint32_t smb = smem_u32(smc);

    const int p   = blockIdx.x;
    const int set = p >> 10;
    const int m   = p & 1023;
    const int n   = m >> 2;
    const int b   = m & 3;
    const float* img = set ? img_s : img_g;
    const float* kp  = set ? kp_s  : kp_g;

    int sx = (int)floorf(kp[2 * n]     * (float)HW) - SIGMA;
    int sy = (int)floorf(kp[2 * n + 1] * (float)HW) - SIGMA;
    sx = min(max(sx, 0), HW - PATCH);
    sy = min(max(sy, 0), HW - PATCH);

    const int tid = threadIdx.x;
    const int wid = tid >> 5;
    const int lid = tid & 31;

    // ---- async weight-image copies (overlap with patch staging + im2col) ----
    #pragma unroll
    for (int i = 0; i < 6; i++) {
        int idx = tid + i * 512;
        if (idx < 2880)
            cp_async16(smb + W2S_OFF + idx * 16, &g_w2s4[idx]);
    }
    if (tid < 160)
        cp_async16(smb + W1B_OFF + tid * 16, &g_w1b4[tid]);
    asm volatile("cp.async.commit_group;" ::: "memory");

    // ---- stage patch fp32 + biases + qoff table ----
    for (int i = tid; i < 3 * PATCH * PATCH; i += 512) {
        int ic = i / (PATCH * PATCH);
        int r  = i % (PATCH * PATCH);
        int y  = r / PATCH, x = r % PATCH;
        patch[ic * PPL + y * PROW + x] =
            img[(((size_t)b * 3 + ic) * HW + (sy + y)) * HW + (sx + x)];
    }
    qofft[tid]       = quad_row_off(tid);
    qofft[tid + 512] = quad_row_off(tid + 512 < 961 ? tid + 512 : 960);
    if (tid < C1) b1s[tid] = b1[tid];
    else if (tid < C1 + C2) b2s[tid - C1] = b2[tid - C1];
    __syncthreads();

    // ---- im2col 2x2 blocks: A[m=y*31+x][k=ic*9+ky*3+kx] bf16, rows 80B ----
    if (tid < 256) {
        const int by = tid >> 4, bx = tid & 15;
        const int y0 = 2 * by, x0 = 2 * bx;
        const bool y1v = (y0 + 1 < C1H);
        const bool x1v = (x0 + 1 < C1H);

        float ld[3][4][4];
        #pragma unroll
        for (int ic = 0; ic < 3; ic++)
            #pragma unroll
            for (int r = 0; r < 4; r++)
                if (r < 3 || y1v) {
                    const float* rp = &patch[ic * PPL + (y0 + r) * PROW + x0];
                    float2 a = *(const float2*)rp;
                    float2 c = *(const float2*)(rp + 2);
                    ld[ic][r][0] = a.x; ld[ic][r][1] = a.y;
                    ld[ic][r][2] = c.x; ld[ic][r][3] = c.y;
                }

        #pragma unroll
        for (int dy = 0; dy < 2; dy++) {
            if (dy == 1 && !y1v) break;
            #pragma unroll
            for (int dx = 0; dx < 2; dx++) {
                if (dx == 1 && !x1v) break;
                float v[27];
                #pragma unroll
                for (int ic = 0; ic < 3; ic++)
                    #pragma unroll
                    for (int ky = 0; ky < 3; ky++)
                        #pragma unroll
                        for (int kx = 0; kx < 3; kx++)
                            v[ic * 9 + ky * 3 + kx] = ld[ic][ky + dy][kx + dx];
                store_a_row(smc, (y0 + dy) * 31 + (x0 + dx), v);
            }
        }
    }
    asm volatile("cp.async.wait_group 0;" ::: "memory");
    __syncthreads();

    // ---- conv1 GEMM: M=1024 (961 valid), N=32, K=32; warp w -> rows 64w..64w+63
    const uint32_t a_row = (uint32_t)(lid & 15);
    const uint32_t a_kh  = (uint32_t)(lid >> 4);
    const uint32_t b_row = (uint32_t)((lid & 7) + ((lid >> 4) << 3));
    const uint32_t b_kh  = (uint32_t)((lid >> 3) & 1);

    uint32_t qv[4][4][2];
    uint32_t qoff[4][2];
    bool     qok[4][2];
    {
        uint32_t bw[2][2][4];
        #pragma unroll
        for (int ks = 0; ks < 2; ks++)
            #pragma unroll
            for (int g = 0; g < 2; g++)
                ldsm_x4(smb + W1B_OFF + (g * 16 + b_row) * QROW + b_kh * 16 + ks * 32,
                        bw[ks][g][0], bw[ks][g][1], bw[ks][g][2], bw[ks][g][3]);

        float b1c0[4], b1c1[4];
        #pragma unroll
        for (int j = 0; j < 4; j++) {
            int c0 = j * 8 + 2 * (lid & 3);
            b1c0[j] = b1s[c0];
            b1c1[j] = b1s[c0 + 1];
        }

        #pragma unroll
        for (int t = 0; t < 4; t++) {
            const int r0 = wid * 64 + t * 16;
            uint32_t a[2][4];
            #pragma unroll
            for (int ks = 0; ks < 2; ks++)
                ldsm_x4(smb + BUF0_OFF + (r0 + a_row) * QROW + a_kh * 16 + ks * 32,
                        a[ks][0], a[ks][1], a[ks][2], a[ks][3]);
            float d[4][4];
            #pragma unroll
            for (int j = 0; j < 4; j++)
                #pragma unroll
                for (int q = 0; q < 4; q++) d[j][q] = 0.0f;
            #pragma unroll
            for (int ks = 0; ks < 2; ks++)
                #pragma unroll
                for (int g = 0; g < 2; g++) {
                    mma16816(d[2 * g],     a[ks][0], a[ks][1], a[ks][2], a[ks][3],
                             bw[ks][g][0], bw[ks][g][1]);
                    mma16816(d[2 * g + 1], a[ks][0], a[ks][1], a[ks][2], a[ks][3],
                             bw[ks][g][2], bw[ks][g][3]);
                }
            const int m_lo = r0 + (lid >> 2);
            const int m_hi = m_lo + 8;
            qok[t][0]  = (m_lo < 961);
            qok[t][1]  = (m_hi < 961);
            qoff[t][0] = qofft[m_lo];
            qoff[t][1] = qofft[m_hi];
            #pragma unroll
            for (int j = 0; j < 4; j++) {
                qv[t][j][0] = bfpack(fmaxf(d[j][0] + b1c0[j], 0.f),
                                     fmaxf(d[j][1] + b1c1[j], 0.f));
                qv[t][j][1] = bfpack(fmaxf(d[j][2] + b1c0[j], 0.f),
                                     fmaxf(d[j][3] + b1c1[j], 0.f));
            }
        }
    }
    __syncthreads();   // all A reads done -> overwrite buf0 as quadrants

    // ---- scatter conv1 output into quadrant layout ----
    {
        const uint32_t cb = (uint32_t)(2 * (lid & 3)) * 2;
        #pragma unroll
        for (int t = 0; t < 4; t++)
            #pragma unroll
            for (int h = 0; h < 2; h++)
                if (qok[t][h]) {
                    char* base = smc + BUF0_OFF + qoff[t][h] + cb;
                    #pragma unroll
                    for (int j = 0; j < 4; j++)
                        *(uint32_t*)(base + j * 16) = qv[t][j][h];
                }
    }
    __syncthreads();

    // ---- conv2 via mma.sync: m32n32 warp tiles; warp = (mg 0..7, ng 0..1) ----
    float acc[2][4][4];
    #pragma unroll
    for (int t = 0; t < 2; t++)
        #pragma unroll
        for (int j = 0; j < 4; j++)
            #pragma unroll
            for (int q = 0; q < 4; q++) acc[t][j][q] = 0.0f;

    const int mg = wid & 7;
    const int ng = wid >> 3;

    #pragma unroll
    for (int tap = 0; tap < 9; tap++) {
        const int ky = tap / 3, kx = tap - 3 * ky;
        const int quad = ((ky & 1) << 1) | (kx & 1);
        const int d0   = ((ky >> 1) << 4) + (kx >> 1);
        const uint32_t a_base0 = smb + BUF0_OFF +
            (uint32_t)(quad * 256 + (2 * mg) * 16 + d0 + a_row) * QROW + a_kh * 16;
        const uint32_t a_base1 = a_base0 + 16 * QROW;
        const uint32_t b_base  = smb + W2S_OFF +
            (uint32_t)(tap * 64 + 2 * ng * 16 + b_row) * QROW + b_kh * 16;

        #pragma unroll
        for (int ks = 0; ks < 2; ks++) {
            uint32_t a0[4], a1[4];
            ldsm_x4(a_base0 + ks * 32, a0[0], a0[1], a0[2], a0[3]);
            ldsm_x4(a_base1 + ks * 32, a1[0], a1[1], a1[2], a1[3]);
            uint32_t b0[4], b1r[4];
            ldsm_x4(b_base + ks * 32, b0[0], b0[1], b0[2], b0[3]);
            ldsm_x4(b_base + 16 * QROW + ks * 32, b1r[0], b1r[1], b1r[2], b1r[3]);

            mma16816(acc[0][0], a0[0], a0[1], a0[2], a0[3], b0[0],  b0[1]);
            mma16816(acc[0][1], a0[0], a0[1], a0[2], a0[3], b0[2],  b0[3]);
            mma16816(acc[0][2], a0[0], a0[1], a0[2], a0[3], b1r[0], b1r[1]);
            mma16816(acc[0][3], a0[0], a0[1], a0[2], a0[3], b1r[2], b1r[3]);
            mma16816(acc[1][0], a1[0], a1[1], a1[2], a1[3], b0[0],  b0[1]);
            mma16816(acc[1][1], a1[0], a1[1], a1[2], a1[3], b0[2],  b0[3]);
            mma16816(acc[1][2], a1[0], a1[1], a1[2], a1[3], b1r[0], b1r[1]);
            mma16816(acc[1][3], a1[0], a1[1], a1[2], a1[3], b1r[2], b1r[3]);
        }
    }

    // ---- epilogue: relu(D + b2), mask (ox==15 | oy==15), reduce ----
    {
        const bool hi_ok = ((lid >> 2) != 7);
        #pragma unroll
        for (int t = 0; t < 2; t++) {
            const int oy = 2 * mg + t;
            const bool oy_ok = (oy < C2H);
            #pragma unroll
            for (int j = 0; j < 4; j++) {
                int c0 = ng * 32 + j * 8 + 2 * (lid & 3);
                float bb0 = b2s[c0], bb1 = b2s[c0 + 1];
                float sA = 0.0f, sB = 0.0f;
                if (oy_ok) {
                    sA = fmaxf(acc[t][j][0] + bb0, 0.0f);
                    sB = fmaxf(acc[t][j][1] + bb1, 0.0f);
                    if (hi_ok) {
                        sA += fmaxf(acc[t][j][2] + bb0, 0.0f);
                        sB += fmaxf(acc[t][j][3] + bb1, 0.0f);
                    }
                }
                #pragma unroll
                for (int msk = 4; msk <= 16; msk <<= 1) {
                    sA += __shfl_xor_sync(0xffffffffu, sA, msk);
                    sB += __shfl_xor_sync(0xffffffffu, sB, msk);
                }
                if (lid < 4) {
                    part[oy * 64 + c0]     = sA;
                    part[oy * 64 + c0 + 1] = sB;
                }
            }
        }
    }
    __syncthreads();

    if (tid < C2) {
        float s = 0.0f;
        #pragma unroll
        for (int ww = 0; ww < 16; ww++) s += part[ww * 64 + tid];
        g_h[((size_t)set * NPATCH + m) * C2 + tid] = s * (1.0f / 225.0f);
    }
}

// ---------------------------------------------------------------------------
// Kernel B: per-pair projected squared diff + fused final reduction.
// y = wl @ (hg - hs); pairsum = sum y^2. Last block (threadfence reduction)
// sums all pairsums in fixed order and writes the mean. Deterministic.
// ---------------------------------------------------------------------------
__global__ void __launch_bounds__(128)
pair_reduce_kernel(const float* __restrict__ wl, float* __restrict__ out)
{
    __shared__ float d[C2];
    __shared__ float red[OUTF];
    __shared__ bool is_last;
    const int pair = blockIdx.x;
    const int tid  = threadIdx.x;

    const float* hg = &g_h[(size_t)pair * C2];
    const float* hs = &g_h[((size_t)NPATCH + pair) * C2];
    if (tid < C2) d[tid] = hg[tid] - hs[tid];
    __syncthreads();

    float y = 0.0f;
    const float* wr = &wl[tid * C2];
    #pragma unroll
    for (int i = 0; i < C2; i++) y += wr[i] * d[i];
    red[tid] = y * y;
    __syncthreads();
    #pragma unroll
    for (int s = OUTF / 2; s > 0; s >>= 1) {
        if (tid < s) red[tid] += red[tid + s];
        __syncthreads();
    }
    if (tid == 0) {
        g_pairsum[pair] = red[0];
        __threadfence();
        unsigned int t = atomicAdd(&g_done_ctr, 1u);
        is_last = (t == NPATCH - 1);
    }
    __syncthreads();

    if (is_last) {
        __threadfence();
        float s = 0.0f;
        for (int i = tid; i < NPATCH; i += 128) s += g_pairsum[i];
        red[tid] = s;
        __syncthreads();
        #pragma unroll
        for (int st = 64; st > 0; st >>= 1) {
            if (tid < st) red[tid] += red[tid + st];
            __syncthreads();
        }
        if (tid == 0) {
            out[0] = red[0] / (float)((size_t)NPATCH * OUTF);
            g_done_ctr = 0;      // reset for next graph replay
        }
    }
}

// ---------------------------------------------------------------------------
extern "C" void kernel_launch(void* const* d_in, const int* in_sizes, int n_in,
                              void* d_out, int out_size)
{
    const float* img_g = (const float*)d_in[0];
    const float* img_s = (const float*)d_in[1];
    const float* kp_g  = (const float*)d_in[2];
    const float* kp_s  = (const float*)d_in[3];
    const float* w1    = (const float*)d_in[4];
    const float* b1    = (const float*)d_in[5];
    const float* w2    = (const float*)d_in[6];
    const float* b2    = (const float*)d_in[7];
    const float* wl    = (const float*)d_in[8];
    // d_in[9] = bl (cancels), d_in[10] = num_samples (fixed)

    cudaFuncSetAttribute(patch_cnn_kernel,
                         cudaFuncAttributeMaxDynamicSharedMemorySize, SMEM_BYTES);

    prep_kernel<<<32, 512>>>(w1, w2);
    patch_cnn_kernel<<<2 * NPATCH, 512, SMEM_BYTES>>>(img_g, img_s, kp_g, kp_s,
                                                      b1, b2);
    pair_reduce_kernel<<<NPATCH, 128>>>(wl, (float*)d_out);
}

// round 13
// speedup vs baseline: 1.0996x; 1.0996x over previous
#include <cuda_runtime.h>
#include <cuda_bf16.h>
#include <cstdint>

// Fixed problem shapes
#define SIGMA   16
#define PATCH   33
#define HW      256
#define NPATCH  1024
#define C1      32
#define C1H     31
#define C2      64
#define C2H     15
#define OUTF    128

// conv1 fp32 patch staging (padded rows)
#define PROW    36
#define PPL     (PATCH * PROW)          // 1188 floats / channel

// smem byte layout
#define BUF0_OFF   0
#define QROW       80
#define BUF0_BYTES (1024 * QROW)        // 81920
#define W2S_OFF    81920                // 9*64 rows x 80B = 46080 -> 128000
#define PATCHG_OFF 128000               // 14336
#define PATCHS_OFF 142336               // 14336
#define W1B_OFF    156672               // 2560
#define B1S_OFF    159232               // 128
#define B2S_OFF    159360               // 256
#define QOFFT_OFF  159616               // 4096
#define PART_OFF   163712               // 4096 (also d[] in pair phase)
#define FEAT_OFF   167808               // 2*64*4 = 512
#define WLS_OFF    168320               // 128*65*4 = 33280
#define RED_OFF    201600               // 512
#define SMEM_BYTES 202112

__device__ float g_pairsum[NPATCH];
// pre-converted weight images (bf16, 80B rows) — written by prep_kernel
__device__ uint4 g_w2s4[2880];          // 46080 B
__device__ uint4 g_w1b4[160];           // 2560 B

__device__ __forceinline__ uint32_t smem_u32(const void* p) {
    uint32_t a;
    asm("{ .reg .u64 t; cvta.to.shared.u64 t, %1; cvt.u32.u64 %0, t; }" : "=r"(a) : "l"(p));
    return a;
}

__device__ __forceinline__ void ldsm_x4(uint32_t addr, uint32_t& r0, uint32_t& r1,
                                        uint32_t& r2, uint32_t& r3) {
    asm volatile("ldmatrix.sync.aligned.m8n8.x4.shared.b16 {%0,%1,%2,%3}, [%4];"
                 : "=r"(r0), "=r"(r1), "=r"(r2), "=r"(r3) : "r"(addr));
}

__device__ __forceinline__ void mma16816(float* d, uint32_t a0, uint32_t a1,
                                         uint32_t a2, uint32_t a3,
                                         uint32_t b0, uint32_t b1) {
    asm volatile("mma.sync.aligned.m16n8k16.row.col.f32.bf16.bf16.f32 "
                 "{%0,%1,%2,%3}, {%4,%5,%6,%7}, {%8,%9}, {%0,%1,%2,%3};"
                 : "+f"(d[0]), "+f"(d[1]), "+f"(d[2]), "+f"(d[3])
                 : "r"(a0), "r"(a1), "r"(a2), "r"(a3), "r"(b0), "r"(b1));
}

__device__ __forceinline__ uint32_t bfpack(float lo, float hi) {
    __nv_bfloat162 v = __floats2bfloat162_rn(lo, hi);
    return *(uint32_t*)&v;
}

__device__ __forceinline__ void cp_async16(uint32_t dst, const void* src) {
    asm volatile("cp.async.ca.shared.global [%0], [%1], 16;" :: "r"(dst), "l"(src));
}

// quadrant smem row byte-offset for conv1-output pixel m = y*31+x
__device__ __forceinline__ uint32_t quad_row_off(int m) {
    int y = m / 31;
    int x = m - 31 * y;
    int row = ((((y & 1) << 1) | (x & 1)) << 8) + ((y >> 1) << 4) + (x >> 1);
    return (uint32_t)row * QROW;
}

// pack 27-tap fp32 vector -> 64B bf16 A row (stride 80B)
__device__ __forceinline__ void store_a_row(char* smc, int mm, const float* v) {
    uint32_t r[16];
    #pragma unroll
    for (int i = 0; i < 13; i++) r[i] = bfpack(v[2 * i], v[2 * i + 1]);
    r[13] = bfpack(v[26], 0.f);
    r[14] = 0u; r[15] = 0u;
    uint4* dst = (uint4*)(smc + BUF0_OFF + mm * QROW);
    dst[0] = make_uint4(r[0], r[1], r[2], r[3]);
    dst[1] = make_uint4(r[4], r[5], r[6], r[7]);
    dst[2] = make_uint4(r[8], r[9], r[10], r[11]);
    dst[3] = make_uint4(r[12], r[13], r[14], r[15]);
}

// ---------------------------------------------------------------------------
// Prep kernel: convert w1/w2 into bf16 smem-image layouts once (32 blocks).
// ---------------------------------------------------------------------------
__global__ void __launch_bounds__(512)
prep_kernel(const float* __restrict__ w1, const float* __restrict__ w2)
{
    const int i = blockIdx.x * 512 + threadIdx.x;
    if (i < 11520) {
        int row = i / 20, c = i - row * 20;
        uint32_t val = 0u;
        if (c < 16) {
            int tap = row >> 6, oc = row & 63;
            int ky = tap / 3, kx = tap - 3 * ky;
            const float* ws = w2 + ((size_t)(oc * C1 + 2 * c) * 3 + ky) * 3 + kx;
            val = bfpack(ws[0], ws[9]);
        }
        ((uint32_t*)g_w2s4)[i] = val;
    }
    if (i < 640) {
        int oc = i / 20, c = i - oc * 20;
        uint32_t val = 0u;
        if (c < 16) {
            float lo = (2 * c     < 27) ? w1[oc * 27 + 2 * c]     : 0.f;
            float hi = (2 * c + 1 < 27) ? w1[oc * 27 + 2 * c + 1] : 0.f;
            val = bfpack(lo, hi);
        }
        ((uint32_t*)g_w1b4)[i] = val;
    }
}

// ---------------------------------------------------------------------------
// Kernel A: one block per PAIR (1024 x 512). Runs the patch CNN twice
// (ground, satellite), then computes sum((wl @ (hg - hs))^2) in-block.
// ---------------------------------------------------------------------------
__global__ void __launch_bounds__(512, 1)
pair_cnn_kernel(const float* __restrict__ img_g, const float* __restrict__ img_s,
                const float* __restrict__ kp_g,  const float* __restrict__ kp_s,
                const float* __restrict__ b1,    const float* __restrict__ b2,
                const float* __restrict__ wl)
{
    extern __shared__ char smc[];
    float* b1s   = (float*)(smc + B1S_OFF);
    float* b2s   = (float*)(smc + B2S_OFF);
    float* part  = (float*)(smc + PART_OFF);
    float* feat  = (float*)(smc + FEAT_OFF);
    float* wls   = (float*)(smc + WLS_OFF);
    float* red   = (float*)(smc + RED_OFF);
    uint32_t* qofft = (uint32_t*)(smc + QOFFT_OFF);
    const uint32_t smb = smem_u32(smc);

    const int m = blockIdx.x;      // pair index
    const int n = m >> 2;
    const int b = m & 3;

    const int tid = threadIdx.x;
    const int wid = tid >> 5;
    const int lid = tid & 31;

    // ---- async weight-image copies ----
    #pragma unroll
    for (int i = 0; i < 6; i++) {
        int idx = tid + i * 512;
        if (idx < 2880)
            cp_async16(smb + W2S_OFF + idx * 16, &g_w2s4[idx]);
    }
    if (tid < 160)
        cp_async16(smb + W1B_OFF + tid * 16, &g_w1b4[tid]);
    asm volatile("cp.async.commit_group;" ::: "memory");

    // ---- stage BOTH patches fp32 (prefetch), wl, biases, qoff table ----
    int sxy[2][2];
    {
        float gx = kp_g[2 * n], gy = kp_g[2 * n + 1];
        float sx_ = kp_s[2 * n], sy_ = kp_s[2 * n + 1];
        sxy[0][0] = min(max((int)floorf(gx * (float)HW) - SIGMA, 0), HW - PATCH);
        sxy[0][1] = min(max((int)floorf(gy * (float)HW) - SIGMA, 0), HW - PATCH);
        sxy[1][0] = min(max((int)floorf(sx_ * (float)HW) - SIGMA, 0), HW - PATCH);
        sxy[1][1] = min(max((int)floorf(sy_ * (float)HW) - SIGMA, 0), HW - PATCH);
    }
    #pragma unroll
    for (int s = 0; s < 2; s++) {
        const float* img = s ? img_s : img_g;
        float* pb = (float*)(smc + (s ? PATCHS_OFF : PATCHG_OFF));
        const int sx = sxy[s][0], sy = sxy[s][1];
        for (int i = tid; i < 3 * PATCH * PATCH; i += 512) {
            int ic = i / (PATCH * PATCH);
            int r  = i % (PATCH * PATCH);
            int y  = r / PATCH, x = r % PATCH;
            pb[ic * PPL + y * PROW + x] =
                img[(((size_t)b * 3 + ic) * HW + (sy + y)) * HW + (sx + x)];
        }
    }
    for (int i = tid; i < OUTF * C2; i += 512)
        wls[(i >> 6) * 65 + (i & 63)] = wl[i];
    qofft[tid]       = quad_row_off(tid);
    qofft[tid + 512] = quad_row_off(tid + 512 < 961 ? tid + 512 : 960);
    if (tid < C1) b1s[tid] = b1[tid];
    else if (tid < C1 + C2) b2s[tid - C1] = b2[tid - C1];
    __syncthreads();

    const uint32_t a_row = (uint32_t)(lid & 15);
    const uint32_t a_kh  = (uint32_t)(lid >> 4);
    const uint32_t b_row = (uint32_t)((lid & 7) + ((lid >> 4) << 3));
    const uint32_t b_kh  = (uint32_t)((lid >> 3) & 1);

    bool waited = false;

    // =================== per-set CNN pipeline (g then s) ===================
    for (int s = 0; s < 2; s++) {
        float* pb = (float*)(smc + (s ? PATCHS_OFF : PATCHG_OFF));

        // ---- im2col 2x2 blocks ----
        if (tid < 256) {
            const int by = tid >> 4, bx = tid & 15;
            const int y0 = 2 * by, x0 = 2 * bx;
            const bool y1v = (y0 + 1 < C1H);
            const bool x1v = (x0 + 1 < C1H);

            float ld[3][4][4];
            #pragma unroll
            for (int ic = 0; ic < 3; ic++)
                #pragma unroll
                for (int r = 0; r < 4; r++)
                    if (r < 3 || y1v) {
                        const float* rp = &pb[ic * PPL + (y0 + r) * PROW + x0];
                        float2 a = *(const float2*)rp;
                        float2 c = *(const float2*)(rp + 2);
                        ld[ic][r][0] = a.x; ld[ic][r][1] = a.y;
                        ld[ic][r][2] = c.x; ld[ic][r][3] = c.y;
                    }

            #pragma unroll
            for (int dy = 0; dy < 2; dy++) {
                if (dy == 1 && !y1v) break;
                #pragma unroll
                for (int dx = 0; dx < 2; dx++) {
                    if (dx == 1 && !x1v) break;
                    float v[27];
                    #pragma unroll
                    for (int ic = 0; ic < 3; ic++)
                        #pragma unroll
                        for (int ky = 0; ky < 3; ky++)
                            #pragma unroll
                            for (int kx = 0; kx < 3; kx++)
                                v[ic * 9 + ky * 3 + kx] = ld[ic][ky + dy][kx + dx];
                    store_a_row(smc, (y0 + dy) * 31 + (x0 + dx), v);
                }
            }
        }
        if (!waited) {
            asm volatile("cp.async.wait_group 0;" ::: "memory");
            waited = true;
        }
        __syncthreads();

        // ---- conv1 GEMM ----
        uint32_t qv[4][4][2];
        uint32_t qoff[4][2];
        bool     qok[4][2];
        {
            uint32_t bw[2][2][4];
            #pragma unroll
            for (int ks = 0; ks < 2; ks++)
                #pragma unroll
                for (int g = 0; g < 2; g++)
                    ldsm_x4(smb + W1B_OFF + (g * 16 + b_row) * QROW + b_kh * 16 + ks * 32,
                            bw[ks][g][0], bw[ks][g][1], bw[ks][g][2], bw[ks][g][3]);

            float b1c0[4], b1c1[4];
            #pragma unroll
            for (int j = 0; j < 4; j++) {
                int c0 = j * 8 + 2 * (lid & 3);
                b1c0[j] = b1s[c0];
                b1c1[j] = b1s[c0 + 1];
            }

            #pragma unroll
            for (int t = 0; t < 4; t++) {
                const int r0 = wid * 64 + t * 16;
                uint32_t a[2][4];
                #pragma unroll
                for (int ks = 0; ks < 2; ks++)
                    ldsm_x4(smb + BUF0_OFF + (r0 + a_row) * QROW + a_kh * 16 + ks * 32,
                            a[ks][0], a[ks][1], a[ks][2], a[ks][3]);
                float d[4][4];
                #pragma unroll
                for (int j = 0; j < 4; j++)
                    #pragma unroll
                    for (int q = 0; q < 4; q++) d[j][q] = 0.0f;
                #pragma unroll
                for (int ks = 0; ks < 2; ks++)
                    #pragma unroll
                    for (int g = 0; g < 2; g++) {
                        mma16816(d[2 * g],     a[ks][0], a[ks][1], a[ks][2], a[ks][3],
                                 bw[ks][g][0], bw[ks][g][1]);
                        mma16816(d[2 * g + 1], a[ks][0], a[ks][1], a[ks][2], a[ks][3],
                                 bw[ks][g][2], bw[ks][g][3]);
                    }
                const int m_lo = r0 + (lid >> 2);
                const int m_hi = m_lo + 8;
                qok[t][0]  = (m_lo < 961);
                qok[t][1]  = (m_hi < 961);
                qoff[t][0] = qofft[m_lo];
                qoff[t][1] = qofft[m_hi];
                #pragma unroll
                for (int j = 0; j < 4; j++) {
                    qv[t][j][0] = bfpack(fmaxf(d[j][0] + b1c0[j], 0.f),
                                         fmaxf(d[j][1] + b1c1[j], 0.f));
                    qv[t][j][1] = bfpack(fmaxf(d[j][2] + b1c0[j], 0.f),
                                         fmaxf(d[j][3] + b1c1[j], 0.f));
                }
            }
        }
        __syncthreads();   // all A reads done -> overwrite buf0 as quadrants

        // ---- scatter conv1 output into quadrant layout ----
        {
            const uint32_t cb = (uint32_t)(2 * (lid & 3)) * 2;
            #pragma unroll
            for (int t = 0; t < 4; t++)
                #pragma unroll
                for (int h = 0; h < 2; h++)
                    if (qok[t][h]) {
                        char* base = smc + BUF0_OFF + qoff[t][h] + cb;
                        #pragma unroll
                        for (int j = 0; j < 4; j++)
                            *(uint32_t*)(base + j * 16) = qv[t][j][h];
                    }
        }
        __syncthreads();

        // ---- conv2 via mma.sync: m32n32 warp tiles ----
        float acc[2][4][4];
        #pragma unroll
        for (int t = 0; t < 2; t++)
            #pragma unroll
            for (int j = 0; j < 4; j++)
                #pragma unroll
                for (int q = 0; q < 4; q++) acc[t][j][q] = 0.0f;

        const int mg = wid & 7;
        const int ng = wid >> 3;

        #pragma unroll
        for (int tap = 0; tap < 9; tap++) {
            const int ky = tap / 3, kx = tap - 3 * ky;
            const int quad = ((ky & 1) << 1) | (kx & 1);
            const int d0   = ((ky >> 1) << 4) + (kx >> 1);
            const uint32_t a_base0 = smb + BUF0_OFF +
                (uint32_t)(quad * 256 + (2 * mg) * 16 + d0 + a_row) * QROW + a_kh * 16;
            const uint32_t a_base1 = a_base0 + 16 * QROW;
            const uint32_t b_base  = smb + W2S_OFF +
                (uint32_t)(tap * 64 + 2 * ng * 16 + b_row) * QROW + b_kh * 16;

            #pragma unroll
            for (int ks = 0; ks < 2; ks++) {
                uint32_t a0[4], a1[4];
                ldsm_x4(a_base0 + ks * 32, a0[0], a0[1], a0[2], a0[3]);
                ldsm_x4(a_base1 + ks * 32, a1[0], a1[1], a1[2], a1[3]);
                uint32_t b0[4], b1r[4];
                ldsm_x4(b_base + ks * 32, b0[0], b0[1], b0[2], b0[3]);
                ldsm_x4(b_base + 16 * QROW + ks * 32, b1r[0], b1r[1], b1r[2], b1r[3]);

                mma16816(acc[0][0], a0[0], a0[1], a0[2], a0[3], b0[0],  b0[1]);
                mma16816(acc[0][1], a0[0], a0[1], a0[2], a0[3], b0[2],  b0[3]);
                mma16816(acc[0][2], a0[0], a0[1], a0[2], a0[3], b1r[0], b1r[1]);
                mma16816(acc[0][3], a0[0], a0[1], a0[2], a0[3], b1r[2], b1r[3]);
                mma16816(acc[1][0], a1[0], a1[1], a1[2], a1[3], b0[0],  b0[1]);
                mma16816(acc[1][1], a1[0], a1[1], a1[2], a1[3], b0[2],  b0[3]);
                mma16816(acc[1][2], a1[0], a1[1], a1[2], a1[3], b1r[0], b1r[1]);
                mma16816(acc[1][3], a1[0], a1[1], a1[2], a1[3], b1r[2], b1r[3]);
            }
        }

        // ---- epilogue: relu(D + b2), mask (ox==15 | oy==15), reduce ----
        {
            const bool hi_ok = ((lid >> 2) != 7);
            #pragma unroll
            for (int t = 0; t < 2; t++) {
                const int oy = 2 * mg + t;
                const bool oy_ok = (oy < C2H);
                #pragma unroll
                for (int j = 0; j < 4; j++) {
                    int c0 = ng * 32 + j * 8 + 2 * (lid & 3);
                    float bb0 = b2s[c0], bb1 = b2s[c0 + 1];
                    float sA = 0.0f, sB = 0.0f;
                    if (oy_ok) {
                        sA = fmaxf(acc[t][j][0] + bb0, 0.0f);
                        sB = fmaxf(acc[t][j][1] + bb1, 0.0f);
                        if (hi_ok) {
                            sA += fmaxf(acc[t][j][2] + bb0, 0.0f);
                            sB += fmaxf(acc[t][j][3] + bb1, 0.0f);
                        }
                    }
                    #pragma unroll
                    for (int msk = 4; msk <= 16; msk <<= 1) {
                        sA += __shfl_xor_sync(0xffffffffu, sA, msk);
                        sB += __shfl_xor_sync(0xffffffffu, sB, msk);
                    }
                    if (lid < 4) {
                        part[oy * 64 + c0]     = sA;
                        part[oy * 64 + c0 + 1] = sB;
                    }
                }
            }
        }
        __syncthreads();

        if (tid < C2) {
            float fsum = 0.0f;
            #pragma unroll
            for (int ww = 0; ww < 16; ww++) fsum += part[ww * 64 + tid];
            feat[s * C2 + tid] = fsum * (1.0f / 225.0f);
        }
        __syncthreads();
    }

    // =================== pair loss: sum((wl @ (hg - hs))^2) ===================
    if (tid < C2) part[tid] = feat[tid] - feat[C2 + tid];   // d[64]
    __syncthreads();

    {
        const int j   = tid >> 2;       // output 0..127
        const int seg = tid & 3;        // 16-wide K segment
        float y = 0.0f;
        const float* wr = &wls[j * 65 + seg * 16];
        const float* dd = &part[seg * 16];
        #pragma unroll
        for (int i = 0; i < 16; i++) y += wr[i] * dd[i];
        y += __shfl_xor_sync(0xffffffffu, y, 1);
        y += __shfl_xor_sync(0xffffffffu, y, 2);
        if (seg == 0) red[j] = y * y;
    }
    __syncthreads();
    #pragma unroll
    for (int st = 64; st > 0; st >>= 1) {
        if (tid < st) red[tid] += red[tid + st];
        __syncthreads();
    }
    if (tid == 0) g_pairsum[m] = red[0];
}

// ---------------------------------------------------------------------------
// Kernel C: final deterministic reduction + mean.
// ---------------------------------------------------------------------------
__global__ void __launch_bounds__(256)
reduce_kernel(float* __restrict__ out)
{
    __shared__ float red[256];
    const int tid = threadIdx.x;
    float s = 0.0f;
    for (int i = tid; i < NPATCH; i += 256) s += g_pairsum[i];
    red[tid] = s;
    __syncthreads();
    #pragma unroll
    for (int st = 128; st > 0; st >>= 1) {
        if (tid < st) red[tid] += red[tid + st];
        __syncthreads();
    }
    if (tid == 0)
        out[0] = red[0] / (float)((size_t)NPATCH * OUTF);
}

// ---------------------------------------------------------------------------
extern "C" void kernel_launch(void* const* d_in, const int* in_sizes, int n_in,
                              void* d_out, int out_size)
{
    const float* img_g = (const float*)d_in[0];
    const float* img_s = (const float*)d_in[1];
    const float* kp_g  = (const float*)d_in[2];
    const float* kp_s  = (const float*)d_in[3];
    const float* w1    = (const float*)d_in[4];
    const float* b1    = (const float*)d_in[5];
    const float* w2    = (const float*)d_in[6];
    const float* b2    = (const float*)d_in[7];
    const float* wl    = (const float*)d_in[8];
    // d_in[9] = bl (cancels), d_in[10] = num_samples (fixed)

    cudaFuncSetAttribute(pair_cnn_kernel,
                         cudaFuncAttributeMaxDynamicSharedMemorySize, SMEM_BYTES);

    prep_kernel<<<32, 512>>>(w1, w2);
    pair_cnn_kernel<<<NPATCH, 512, SMEM_BYTES>>>(img_g, img_s, kp_g, kp_s,
                                                 b1, b2, wl);
    reduce_kernel<<<1, 256>>>((float*)d_out);
}

// round 14
// speedup vs baseline: 1.1304x; 1.0280x over previous
#include <cuda_runtime.h>
#include <cuda_bf16.h>
#include <cstdint>

// Fixed problem shapes
#define SIGMA   16
#define PATCH   33
#define HW      256
#define NPATCH  1024
#define C1      32
#define C1H     31
#define C2      64
#define C2H     15
#define OUTF    128

// conv1 fp32 patch staging (padded rows)
#define PROW    36
#define PPL     (PATCH * PROW)          // 1188 floats / channel

// smem byte layout
//  two quad/A buffers: 1024 rows x 64B, XOR-swizzled (chunk ^= (row>>1)&3)
#define QG_OFF     0
#define QS_OFF     65536
#define W2S_OFF    131072               // 9*64 rows x 80B = 46080
#define PATCHG_OFF 177152               // 14336
#define PATCHS_OFF 191488               // 14336
#define W1B_OFF    205824               // 32 rows x 80B = 2560
#define B1S_OFF    208384               // 128
#define B2S_OFF    208512               // 256
#define QOFFT_OFF  208768               // 4096
#define PART_OFF   212864               // 4096 (also d[] in pair phase)
#define FEAT_OFF   216960               // 512
#define RED_OFF    217472               // 512
#define SMEM_BYTES 217984

__device__ float g_pairsum[NPATCH];
// pre-converted weight images (bf16, 80B rows) — written by prep_kernel
__device__ uint4 g_w2s4[2880];          // 46080 B
__device__ uint4 g_w1b4[160];           // 2560 B

__device__ __forceinline__ uint32_t smem_u32(const void* p) {
    uint32_t a;
    asm("{ .reg .u64 t; cvta.to.shared.u64 t, %1; cvt.u32.u64 %0, t; }" : "=r"(a) : "l"(p));
    return a;
}

__device__ __forceinline__ void ldsm_x4(uint32_t addr, uint32_t& r0, uint32_t& r1,
                                        uint32_t& r2, uint32_t& r3) {
    asm volatile("ldmatrix.sync.aligned.m8n8.x4.shared.b16 {%0,%1,%2,%3}, [%4];"
                 : "=r"(r0), "=r"(r1), "=r"(r2), "=r"(r3) : "r"(addr));
}

__device__ __forceinline__ void mma16816(float* d, uint32_t a0, uint32_t a1,
                                         uint32_t a2, uint32_t a3,
                                         uint32_t b0, uint32_t b1) {
    asm volatile("mma.sync.aligned.m16n8k16.row.col.f32.bf16.bf16.f32 "
                 "{%0,%1,%2,%3}, {%4,%5,%6,%7}, {%8,%9}, {%0,%1,%2,%3};"
                 : "+f"(d[0]), "+f"(d[1]), "+f"(d[2]), "+f"(d[3])
                 : "r"(a0), "r"(a1), "r"(a2), "r"(a3), "r"(b0), "r"(b1));
}

__device__ __forceinline__ uint32_t bfpack(float lo, float hi) {
    __nv_bfloat162 v = __floats2bfloat162_rn(lo, hi);
    return *(uint32_t*)&v;
}

__device__ __forceinline__ void cp_async16(uint32_t dst, const void* src) {
    asm volatile("cp.async.ca.shared.global [%0], [%1], 16;" :: "r"(dst), "l"(src));
}

// quadrant row byte-offset (row*64) for conv1-output pixel m = y*31+x
__device__ __forceinline__ uint32_t quad_row_off(int m) {
    int y = m / 31;
    int x = m - 31 * y;
    int row = ((((y & 1) << 1) | (x & 1)) << 8) + ((y >> 1) << 4) + (x >> 1);
    return (uint32_t)row * 64;
}

// pack 27-tap fp32 vector -> 64B bf16 A row, XOR chunk swizzle
__device__ __forceinline__ void store_a_row(char* smc, uint32_t bufoff, int mm,
                                            const float* v) {
    uint32_t r[16];
    #pragma unroll
    for (int i = 0; i < 13; i++) r[i] = bfpack(v[2 * i], v[2 * i + 1]);
    r[13] = bfpack(v[26], 0.f);
    r[14] = 0u; r[15] = 0u;
    uint32_t sw = ((uint32_t)mm >> 1) & 3u;
    uint4* dst = (uint4*)(smc + bufoff + (uint32_t)mm * 64);
    uint4 c0 = make_uint4(r[0], r[1], r[2], r[3]);
    uint4 c1 = make_uint4(r[4], r[5], r[6], r[7]);
    uint4 c2 = make_uint4(r[8], r[9], r[10], r[11]);
    uint4 c3 = make_uint4(r[12], r[13], r[14], r[15]);
    dst[0 ^ sw] = c0; dst[1 ^ sw] = c1; dst[2 ^ sw] = c2; dst[3 ^ sw] = c3;
}

// ---------------------------------------------------------------------------
// Prep kernel: convert w1/w2 into bf16 smem-image layouts once (32 blocks).
// ---------------------------------------------------------------------------
__global__ void __launch_bounds__(512)
prep_kernel(const float* __restrict__ w1, const float* __restrict__ w2)
{
    const int i = blockIdx.x * 512 + threadIdx.x;
    if (i < 11520) {
        int row = i / 20, c = i - row * 20;
        uint32_t val = 0u;
        if (c < 16) {
            int tap = row >> 6, oc = row & 63;
            int ky = tap / 3, kx = tap - 3 * ky;
            const float* ws = w2 + ((size_t)(oc * C1 + 2 * c) * 3 + ky) * 3 + kx;
            val = bfpack(ws[0], ws[9]);
        }
        ((uint32_t*)g_w2s4)[i] = val;
    }
    if (i < 640) {
        int oc = i / 20, c = i - oc * 20;
        uint32_t val = 0u;
        if (c < 16) {
            float lo = (2 * c     < 27) ? w1[oc * 27 + 2 * c]     : 0.f;
            float hi = (2 * c + 1 < 27) ? w1[oc * 27 + 2 * c + 1] : 0.f;
            val = bfpack(lo, hi);
        }
        ((uint32_t*)g_w1b4)[i] = val;
    }
}

// ---------------------------------------------------------------------------
// Kernel A: one block per PAIR (1024 x 512). Both sets' quadrant buffers kept
// resident; single conv2 pass shares B fragments across sets.
// ---------------------------------------------------------------------------
__global__ void __launch_bounds__(512, 1)
pair_cnn_kernel(const float* __restrict__ img_g, const float* __restrict__ img_s,
                const float* __restrict__ kp_g,  const float* __restrict__ kp_s,
                const float* __restrict__ b1,    const float* __restrict__ b2,
                const float* __restrict__ wl)
{
    extern __shared__ char smc[];
    float* b1s   = (float*)(smc + B1S_OFF);
    float* b2s   = (float*)(smc + B2S_OFF);
    float* part  = (float*)(smc + PART_OFF);
    float* feat  = (float*)(smc + FEAT_OFF);
    float* red   = (float*)(smc + RED_OFF);
    uint32_t* qofft = (uint32_t*)(smc + QOFFT_OFF);
    const uint32_t smb = smem_u32(smc);

    const int m = blockIdx.x;      // pair index
    const int n = m >> 2;
    const int b = m & 3;

    const int tid = threadIdx.x;
    const int wid = tid >> 5;
    const int lid = tid & 31;

    // ---- async weight-image copies ----
    #pragma unroll
    for (int i = 0; i < 6; i++) {
        int idx = tid + i * 512;
        if (idx < 2880)
            cp_async16(smb + W2S_OFF + idx * 16, &g_w2s4[idx]);
    }
    if (tid < 160)
        cp_async16(smb + W1B_OFF + tid * 16, &g_w1b4[tid]);
    asm volatile("cp.async.commit_group;" ::: "memory");

    // ---- stage BOTH patches fp32 (prefetch), biases, qoff table ----
    int sxy[2][2];
    {
        float gx = kp_g[2 * n], gy = kp_g[2 * n + 1];
        float sx_ = kp_s[2 * n], sy_ = kp_s[2 * n + 1];
        sxy[0][0] = min(max((int)floorf(gx * (float)HW) - SIGMA, 0), HW - PATCH);
        sxy[0][1] = min(max((int)floorf(gy * (float)HW) - SIGMA, 0), HW - PATCH);
        sxy[1][0] = min(max((int)floorf(sx_ * (float)HW) - SIGMA, 0), HW - PATCH);
        sxy[1][1] = min(max((int)floorf(sy_ * (float)HW) - SIGMA, 0), HW - PATCH);
    }
    #pragma unroll
    for (int s = 0; s < 2; s++) {
        const float* img = s ? img_s : img_g;
        float* pb = (float*)(smc + (s ? PATCHS_OFF : PATCHG_OFF));
        const int sx = sxy[s][0], sy = sxy[s][1];
        for (int i = tid; i < 3 * PATCH * PATCH; i += 512) {
            int ic = i / (PATCH * PATCH);
            int r  = i % (PATCH * PATCH);
            int y  = r / PATCH, x = r % PATCH;
            pb[ic * PPL + y * PROW + x] =
                img[(((size_t)b * 3 + ic) * HW + (sy + y)) * HW + (sx + x)];
        }
    }
    qofft[tid]       = quad_row_off(tid);
    qofft[tid + 512] = quad_row_off(tid + 512 < 961 ? tid + 512 : 960);
    if (tid < C1) b1s[tid] = b1[tid];
    else if (tid < C1 + C2) b2s[tid - C1] = b2[tid - C1];
    __syncthreads();

    const uint32_t arow_lane = (uint32_t)(lid & 15);
    const uint32_t a_kh  = (uint32_t)(lid >> 4);
    const uint32_t b_row = (uint32_t)((lid & 7) + ((lid >> 4) << 3));
    const uint32_t b_kh  = (uint32_t)((lid >> 3) & 1);

    bool waited = false;

    // ========== per-set: im2col -> conv1 -> scatter into quad buffer ==========
    for (int s = 0; s < 2; s++) {
        float* pb = (float*)(smc + (s ? PATCHS_OFF : PATCHG_OFF));
        const uint32_t qb_off = s ? QS_OFF : QG_OFF;
        const uint32_t qb = smb + qb_off;

        // ---- im2col 2x2 blocks ----
        if (tid < 256) {
            const int by = tid >> 4, bx = tid & 15;
            const int y0 = 2 * by, x0 = 2 * bx;
            const bool y1v = (y0 + 1 < C1H);
            const bool x1v = (x0 + 1 < C1H);

            float ld[3][4][4];
            #pragma unroll
            for (int ic = 0; ic < 3; ic++)
                #pragma unroll
                for (int r = 0; r < 4; r++)
                    if (r < 3 || y1v) {
                        const float* rp = &pb[ic * PPL + (y0 + r) * PROW + x0];
                        float2 a = *(const float2*)rp;
                        float2 c = *(const float2*)(rp + 2);
                        ld[ic][r][0] = a.x; ld[ic][r][1] = a.y;
                        ld[ic][r][2] = c.x; ld[ic][r][3] = c.y;
                    }

            #pragma unroll
            for (int dy = 0; dy < 2; dy++) {
                if (dy == 1 && !y1v) break;
                #pragma unroll
                for (int dx = 0; dx < 2; dx++) {
                    if (dx == 1 && !x1v) break;
                    float v[27];
                    #pragma unroll
                    for (int ic = 0; ic < 3; ic++)
                        #pragma unroll
                        for (int ky = 0; ky < 3; ky++)
                            #pragma unroll
                            for (int kx = 0; kx < 3; kx++)
                                v[ic * 9 + ky * 3 + kx] = ld[ic][ky + dy][kx + dx];
                    store_a_row(smc, qb_off, (y0 + dy) * 31 + (x0 + dx), v);
                }
            }
        }
        if (!waited) {
            asm volatile("cp.async.wait_group 0;" ::: "memory");
            waited = true;
        }
        __syncthreads();

        // ---- conv1 GEMM (M=1024 rows in this buffer, N=32, K=32) ----
        uint32_t qv[4][4][2];
        uint32_t qoff[4][2];
        bool     qok[4][2];
        {
            uint32_t bw[2][2][4];
            #pragma unroll
            for (int ks = 0; ks < 2; ks++)
                #pragma unroll
                for (int g = 0; g < 2; g++)
                    ldsm_x4(smb + W1B_OFF + (g * 16 + b_row) * 80 + b_kh * 16 + ks * 32,
                            bw[ks][g][0], bw[ks][g][1], bw[ks][g][2], bw[ks][g][3]);

            float b1c0[4], b1c1[4];
            #pragma unroll
            for (int j = 0; j < 4; j++) {
                int c0 = j * 8 + 2 * (lid & 3);
                b1c0[j] = b1s[c0];
                b1c1[j] = b1s[c0 + 1];
            }

            #pragma unroll
            for (int t = 0; t < 4; t++) {
                const int r0 = wid * 64 + t * 16;
                const uint32_t row = (uint32_t)r0 + arow_lane;
                const uint32_t sw  = (row >> 1) & 3u;
                const uint32_t rb  = qb + row * 64;
                uint32_t a[2][4];
                #pragma unroll
                for (int ks = 0; ks < 2; ks++)
                    ldsm_x4(rb + ((((uint32_t)ks << 1) | a_kh) ^ sw) * 16,
                            a[ks][0], a[ks][1], a[ks][2], a[ks][3]);
                float d[4][4];
                #pragma unroll
                for (int j = 0; j < 4; j++)
                    #pragma unroll
                    for (int q = 0; q < 4; q++) d[j][q] = 0.0f;
                #pragma unroll
                for (int ks = 0; ks < 2; ks++)
                    #pragma unroll
                    for (int g = 0; g < 2; g++) {
                        mma16816(d[2 * g],     a[ks][0], a[ks][1], a[ks][2], a[ks][3],
                                 bw[ks][g][0], bw[ks][g][1]);
                        mma16816(d[2 * g + 1], a[ks][0], a[ks][1], a[ks][2], a[ks][3],
                                 bw[ks][g][2], bw[ks][g][3]);
                    }
                const int m_lo = r0 + (lid >> 2);
                const int m_hi = m_lo + 8;
                qok[t][0]  = (m_lo < 961);
                qok[t][1]  = (m_hi < 961);
                qoff[t][0] = qofft[m_lo];
                qoff[t][1] = qofft[m_hi];
                #pragma unroll
                for (int j = 0; j < 4; j++) {
                    qv[t][j][0] = bfpack(fmaxf(d[j][0] + b1c0[j], 0.f),
                                         fmaxf(d[j][1] + b1c1[j], 0.f));
                    qv[t][j][1] = bfpack(fmaxf(d[j][2] + b1c0[j], 0.f),
                                         fmaxf(d[j][3] + b1c1[j], 0.f));
                }
            }
        }
        __syncthreads();   // all A reads done -> overwrite buffer as quadrants

        // ---- scatter conv1 output into swizzled quadrant layout ----
        {
            const uint32_t cb = (uint32_t)(lid & 3) * 4;
            #pragma unroll
            for (int t = 0; t < 4; t++)
                #pragma unroll
                for (int h = 0; h < 2; h++)
                    if (qok[t][h]) {
                        const uint32_t ro = qoff[t][h];
                        const uint32_t sw = (ro >> 7) & 3u;
                        char* base = smc + qb_off + ro + cb;
                        #pragma unroll
                        for (int j = 0; j < 4; j++)
                            *(uint32_t*)(base + ((uint32_t)(j ^ sw) * 16)) = qv[t][j][h];
                    }
        }
        __syncthreads();
    }

    // ========== conv2: shared B fragments across both sets ==========
    float acc[2][2][4][4];
    #pragma unroll
    for (int s = 0; s < 2; s++)
        #pragma unroll
        for (int t = 0; t < 2; t++)
            #pragma unroll
            for (int j = 0; j < 4; j++)
                #pragma unroll
                for (int q = 0; q < 4; q++) acc[s][t][j][q] = 0.0f;

    const int mg = wid & 7;
    const int ng = wid >> 3;

    #pragma unroll
    for (int tap = 0; tap < 9; tap++) {
        const int ky = tap / 3, kx = tap - 3 * ky;
        const int quad = ((ky & 1) << 1) | (kx & 1);
        const int d0   = ((ky >> 1) << 4) + (kx >> 1);
        const uint32_t row0 = (uint32_t)(quad * 256 + mg * 32 + d0) + arow_lane;
        const uint32_t sw   = (row0 >> 1) & 3u;
        const uint32_t off0 = row0 * 64;
        const uint32_t b_base = smb + W2S_OFF +
            (uint32_t)(tap * 64 + ng * 32 + b_row) * 80 + b_kh * 16;

        #pragma unroll
        for (int ks = 0; ks < 2; ks++) {
            const uint32_t coff = ((((uint32_t)ks << 1) | a_kh) ^ sw) * 16;
            uint32_t b0[4], b1r[4];
            ldsm_x4(b_base + ks * 32, b0[0], b0[1], b0[2], b0[3]);
            ldsm_x4(b_base + 16 * 80 + ks * 32, b1r[0], b1r[1], b1r[2], b1r[3]);

            #pragma unroll
            for (int s = 0; s < 2; s++) {
                const uint32_t qb = smb + (s ? QS_OFF : QG_OFF);
                uint32_t a0[4], a1[4];
                ldsm_x4(qb + off0 + coff, a0[0], a0[1], a0[2], a0[3]);
                ldsm_x4(qb + off0 + 1024 + coff, a1[0], a1[1], a1[2], a1[3]);

                mma16816(acc[s][0][0], a0[0], a0[1], a0[2], a0[3], b0[0],  b0[1]);
                mma16816(acc[s][0][1], a0[0], a0[1], a0[2], a0[3], b0[2],  b0[3]);
                mma16816(acc[s][0][2], a0[0], a0[1], a0[2], a0[3], b1r[0], b1r[1]);
                mma16816(acc[s][0][3], a0[0], a0[1], a0[2], a0[3], b1r[2], b1r[3]);
                mma16816(acc[s][1][0], a1[0], a1[1], a1[2], a1[3], b0[0],  b0[1]);
                mma16816(acc[s][1][1], a1[0], a1[1], a1[2], a1[3], b0[2],  b0[3]);
                mma16816(acc[s][1][2], a1[0], a1[1], a1[2], a1[3], b1r[0], b1r[1]);
                mma16816(acc[s][1][3], a1[0], a1[1], a1[2], a1[3], b1r[2], b1r[3]);
            }
        }
    }

    // ========== epilogues: relu(D + b2), mask, reduce -> feats ==========
    #pragma unroll
    for (int s = 0; s < 2; s++) {
        const bool hi_ok = ((lid >> 2) != 7);
        #pragma unroll
        for (int t = 0; t < 2; t++) {
            const int oy = 2 * mg + t;
            const bool oy_ok = (oy < C2H);
            #pragma unroll
            for (int j = 0; j < 4; j++) {
                int c0 = ng * 32 + j * 8 + 2 * (lid & 3);
                float bb0 = b2s[c0], bb1 = b2s[c0 + 1];
                float sA = 0.0f, sB = 0.0f;
                if (oy_ok) {
                    sA = fmaxf(acc[s][t][j][0] + bb0, 0.0f);
                    sB = fmaxf(acc[s][t][j][1] + bb1, 0.0f);
                    if (hi_ok) {
                        sA += fmaxf(acc[s][t][j][2] + bb0, 0.0f);
                        sB += fmaxf(acc[s][t][j][3] + bb1, 0.0f);
                    }
                }
                #pragma unroll
                for (int msk = 4; msk <= 16; msk <<= 1) {
                    sA += __shfl_xor_sync(0xffffffffu, sA, msk);
                    sB += __shfl_xor_sync(0xffffffffu, sB, msk);
                }
                if (lid < 4) {
                    part[oy * 64 + c0]     = sA;
                    part[oy * 64 + c0 + 1] = sB;
                }
            }
        }
        __syncthreads();
        if (tid < C2) {
            float fsum = 0.0f;
            #pragma unroll
            for (int ww = 0; ww < 16; ww++) fsum += part[ww * 64 + tid];
            feat[s * C2 + tid] = fsum * (1.0f / 225.0f);
        }
        __syncthreads();
    }

    // ========== pair loss: sum((wl @ (hg - hs))^2), wl from global ==========
    if (tid < C2) part[tid] = feat[tid] - feat[C2 + tid];   // d[64]
    __syncthreads();

    {
        const int j   = tid >> 2;       // output 0..127
        const int seg = tid & 3;        // 16-wide K segment
        float y = 0.0f;
        const float* wr = &wl[j * C2 + seg * 16];
        const float* dd = &part[seg * 16];
        #pragma unroll
        for (int i = 0; i < 16; i++) y += wr[i] * dd[i];
        y += __shfl_xor_sync(0xffffffffu, y, 1);
        y += __shfl_xor_sync(0xffffffffu, y, 2);
        if (seg == 0) red[j] = y * y;
    }
    __syncthreads();
    #pragma unroll
    for (int st = 64; st > 0; st >>= 1) {
        if (tid < st) red[tid] += red[tid + st];
        __syncthreads();
    }
    if (tid == 0) g_pairsum[m] = red[0];
}

// ---------------------------------------------------------------------------
// Kernel C: final deterministic reduction + mean.
// ---------------------------------------------------------------------------
__global__ void __launch_bounds__(256)
reduce_kernel(float* __restrict__ out)
{
    __shared__ float red[256];
    const int tid = threadIdx.x;
    float s = 0.0f;
    for (int i = tid; i < NPATCH; i += 256) s += g_pairsum[i];
    red[tid] = s;
    __syncthreads();
    #pragma unroll
    for (int st = 128; st > 0; st >>= 1) {
        if (tid < st) red[tid] += red[tid + st];
        __syncthreads();
    }
    if (tid == 0)
        out[0] = red[0] / (float)((size_t)NPATCH * OUTF);
}

// ---------------------------------------------------------------------------
extern "C" void kernel_launch(void* const* d_in, const int* in_sizes, int n_in,
                              void* d_out, int out_size)
{
    const float* img_g = (const float*)d_in[0];
    const float* img_s = (const float*)d_in[1];
    const float* kp_g  = (const float*)d_in[2];
    const float* kp_s  = (const float*)d_in[3];
    const float* w1    = (const float*)d_in[4];
    const float* b1    = (const float*)d_in[5];
    const float* w2    = (const float*)d_in[6];
    const float* b2    = (const float*)d_in[7];
    const float* wl    = (const float*)d_in[8];
    // d_in[9] = bl (cancels), d_in[10] = num_samples (fixed)

    cudaFuncSetAttribute(pair_cnn_kernel,
                         cudaFuncAttributeMaxDynamicSharedMemorySize, SMEM_BYTES);

    prep_kernel<<<32, 512>>>(w1, w2);
    pair_cnn_kernel<<<NPATCH, 512, SMEM_BYTES>>>(img_g, img_s, kp_g, kp_s,
                                                 b1, b2, wl);
    reduce_kernel<<<1, 256>>>((float*)d_out);
}

// round 15
// speedup vs baseline: 1.1880x; 1.0510x over previous
#include <cuda_runtime.h>
#include <cuda_bf16.h>
#include <cstdint>

// Fixed problem shapes
#define SIGMA   16
#define PATCH   33
#define HW      256
#define NPATCH  1024
#define C1      32
#define C1H     31
#define C2      64
#define C2H     15
#define OUTF    128

// conv1 fp32 patch staging (padded rows)
#define PROW    36
#define PPL     (PATCH * PROW)          // 1188 floats / channel

// smem byte layout
//  two quad/A buffers: 1024 rows x 64B, XOR-swizzled (chunk ^= (row>>1)&3)
#define QG_OFF     0
#define QS_OFF     65536
#define W2S_OFF    131072               // 9*64 rows x 80B = 46080
#define PATCHG_OFF 177152               // 14336
#define PATCHS_OFF 191488               // 14336
#define W1B_OFF    205824               // 32 rows x 80B = 2560
#define B1S_OFF    208384               // 128
#define B2S_OFF    208512               // 256
#define QOFFT_OFF  208768               // 4096 (aliased: part2 in epilogue)
#define PART_OFF   212864               // 4096
#define FEAT_OFF   216960               // 512 (d[] in pair phase)
#define RED_OFF    217472               // 512
#define SMEM_BYTES 217984

__device__ float g_pairsum[NPATCH];
// pre-converted weight images (bf16) — written by prep_kernel
__device__ uint4 g_w2s4[2880];          // 46080 B
__device__ uint4 g_w1b4[160];           // 2560 B

__device__ __forceinline__ uint32_t smem_u32(const void* p) {
    uint32_t a;
    asm("{ .reg .u64 t; cvta.to.shared.u64 t, %1; cvt.u32.u64 %0, t; }" : "=r"(a) : "l"(p));
    return a;
}

__device__ __forceinline__ void ldsm_x4(uint32_t addr, uint32_t& r0, uint32_t& r1,
                                        uint32_t& r2, uint32_t& r3) {
    asm volatile("ldmatrix.sync.aligned.m8n8.x4.shared.b16 {%0,%1,%2,%3}, [%4];"
                 : "=r"(r0), "=r"(r1), "=r"(r2), "=r"(r3) : "r"(addr));
}

__device__ __forceinline__ void mma16816(float* d, uint32_t a0, uint32_t a1,
                                         uint32_t a2, uint32_t a3,
                                         uint32_t b0, uint32_t b1) {
    asm volatile("mma.sync.aligned.m16n8k16.row.col.f32.bf16.bf16.f32 "
                 "{%0,%1,%2,%3}, {%4,%5,%6,%7}, {%8,%9}, {%0,%1,%2,%3};"
                 : "+f"(d[0]), "+f"(d[1]), "+f"(d[2]), "+f"(d[3])
                 : "r"(a0), "r"(a1), "r"(a2), "r"(a3), "r"(b0), "r"(b1));
}

__device__ __forceinline__ uint32_t bfpack(float lo, float hi) {
    __nv_bfloat162 v = __floats2bfloat162_rn(lo, hi);
    return *(uint32_t*)&v;
}

__device__ __forceinline__ void cp_async16(uint32_t dst, const void* src) {
    asm volatile("cp.async.ca.shared.global [%0], [%1], 16;" :: "r"(dst), "l"(src));
}

// quadrant row byte-offset (row*64) for conv1-output pixel m = y*31+x
__device__ __forceinline__ uint32_t quad_row_off(int m) {
    int y = m / 31;
    int x = m - 31 * y;
    int row = ((((y & 1) << 1) | (x & 1)) << 8) + ((y >> 1) << 4) + (x >> 1);
    return (uint32_t)row * 64;
}

// pack 27-tap fp32 vector -> 64B bf16 A row, XOR chunk swizzle
__device__ __forceinline__ void store_a_row(char* smc, uint32_t bufoff, int mm,
                                            const float* v) {
    uint32_t r[16];
    #pragma unroll
    for (int i = 0; i < 13; i++) r[i] = bfpack(v[2 * i], v[2 * i + 1]);
    r[13] = bfpack(v[26], 0.f);
    r[14] = 0u; r[15] = 0u;
    uint32_t sw = ((uint32_t)mm >> 1) & 3u;
    uint4* dst = (uint4*)(smc + bufoff + (uint32_t)mm * 64);
    uint4 c0 = make_uint4(r[0], r[1], r[2], r[3]);
    uint4 c1 = make_uint4(r[4], r[5], r[6], r[7]);
    uint4 c2 = make_uint4(r[8], r[9], r[10], r[11]);
    uint4 c3 = make_uint4(r[12], r[13], r[14], r[15]);
    dst[0 ^ sw] = c0; dst[1 ^ sw] = c1; dst[2 ^ sw] = c2; dst[3 ^ sw] = c3;
}

// ---------------------------------------------------------------------------
// Prep kernel: convert w1/w2 into bf16 smem-image layouts once (32 blocks).
// ---------------------------------------------------------------------------
__global__ void __launch_bounds__(512)
prep_kernel(const float* __restrict__ w1, const float* __restrict__ w2)
{
    const int i = blockIdx.x * 512 + threadIdx.x;
    if (i < 11520) {
        int row = i / 20, c = i - row * 20;
        uint32_t val = 0u;
        if (c < 16) {
            int tap = row >> 6, oc = row & 63;
            int ky = tap / 3, kx = tap - 3 * ky;
            const float* ws = w2 + ((size_t)(oc * C1 + 2 * c) * 3 + ky) * 3 + kx;
            val = bfpack(ws[0], ws[9]);
        }
        ((uint32_t*)g_w2s4)[i] = val;
    }
    if (i < 640) {
        int oc = i / 20, c = i - oc * 20;
        uint32_t val = 0u;
        if (c < 16) {
            float lo = (2 * c     < 27) ? w1[oc * 27 + 2 * c]     : 0.f;
            float hi = (2 * c + 1 < 27) ? w1[oc * 27 + 2 * c + 1] : 0.f;
            val = bfpack(lo, hi);
        }
        ((uint32_t*)g_w1b4)[i] = val;
    }
}

// ---------------------------------------------------------------------------
// Kernel A: one block per PAIR (1024 x 512). Both sets' im2col run
// concurrently; conv2 shares B fragments across sets; fused epilogue.
// ---------------------------------------------------------------------------
__global__ void __launch_bounds__(512, 1)
pair_cnn_kernel(const float* __restrict__ img_g, const float* __restrict__ img_s,
                const float* __restrict__ kp_g,  const float* __restrict__ kp_s,
                const float* __restrict__ b1,    const float* __restrict__ b2,
                const float* __restrict__ wl)
{
    extern __shared__ char smc[];
    float* b1s   = (float*)(smc + B1S_OFF);
    float* b2s   = (float*)(smc + B2S_OFF);
    float* part  = (float*)(smc + PART_OFF);
    float* part2 = (float*)(smc + QOFFT_OFF);   // alias (qofft dead by epilogue)
    float* feat  = (float*)(smc + FEAT_OFF);
    float* red   = (float*)(smc + RED_OFF);
    uint32_t* qofft = (uint32_t*)(smc + QOFFT_OFF);
    const uint32_t smb = smem_u32(smc);

    const int m = blockIdx.x;      // pair index
    const int n = m >> 2;
    const int b = m & 3;

    const int tid = threadIdx.x;
    const int wid = tid >> 5;
    const int lid = tid & 31;

    // ---- async weight-image copies ----
    #pragma unroll
    for (int i = 0; i < 6; i++) {
        int idx = tid + i * 512;
        if (idx < 2880)
            cp_async16(smb + W2S_OFF + idx * 16, &g_w2s4[idx]);
    }
    if (tid < 160)
        cp_async16(smb + W1B_OFF + tid * 16, &g_w1b4[tid]);
    asm volatile("cp.async.commit_group;" ::: "memory");

    // ---- stage BOTH patches fp32, biases, qoff table ----
    int sxy[2][2];
    {
        float gx = kp_g[2 * n], gy = kp_g[2 * n + 1];
        float sx_ = kp_s[2 * n], sy_ = kp_s[2 * n + 1];
        sxy[0][0] = min(max((int)floorf(gx * (float)HW) - SIGMA, 0), HW - PATCH);
        sxy[0][1] = min(max((int)floorf(gy * (float)HW) - SIGMA, 0), HW - PATCH);
        sxy[1][0] = min(max((int)floorf(sx_ * (float)HW) - SIGMA, 0), HW - PATCH);
        sxy[1][1] = min(max((int)floorf(sy_ * (float)HW) - SIGMA, 0), HW - PATCH);
    }
    #pragma unroll
    for (int s = 0; s < 2; s++) {
        const float* img = s ? img_s : img_g;
        float* pb = (float*)(smc + (s ? PATCHS_OFF : PATCHG_OFF));
        const int sx = sxy[s][0], sy = sxy[s][1];
        for (int i = tid; i < 3 * PATCH * PATCH; i += 512) {
            int ic = i / (PATCH * PATCH);
            int r  = i % (PATCH * PATCH);
            int y  = r / PATCH, x = r % PATCH;
            pb[ic * PPL + y * PROW + x] =
                img[(((size_t)b * 3 + ic) * HW + (sy + y)) * HW + (sx + x)];
        }
    }
    qofft[tid]       = quad_row_off(tid);
    qofft[tid + 512] = quad_row_off(tid + 512 < 961 ? tid + 512 : 960);
    if (tid < C1) b1s[tid] = b1[tid];
    else if (tid < C1 + C2) b2s[tid - C1] = b2[tid - C1];
    __syncthreads();

    const uint32_t arow_lane = (uint32_t)(lid & 15);
    const uint32_t a_kh  = (uint32_t)(lid >> 4);
    const uint32_t b_row = (uint32_t)((lid & 7) + ((lid >> 4) << 3));
    const uint32_t b_kh  = (uint32_t)((lid >> 3) & 1);

    // ========== im2col: BOTH sets concurrently (256 threads each) ==========
    {
        const int s  = tid >> 8;           // 0: ground, 1: satellite
        const int tt = tid & 255;
        float* pb = (float*)(smc + (s ? PATCHS_OFF : PATCHG_OFF));
        const uint32_t qb_off = s ? QS_OFF : QG_OFF;

        const int by = tt >> 4, bx = tt & 15;
        const int y0 = 2 * by, x0 = 2 * bx;
        const bool y1v = (y0 + 1 < C1H);
        const bool x1v = (x0 + 1 < C1H);

        float ld[3][4][4];
        #pragma unroll
        for (int ic = 0; ic < 3; ic++)
            #pragma unroll
            for (int r = 0; r < 4; r++)
                if (r < 3 || y1v) {
                    const float* rp = &pb[ic * PPL + (y0 + r) * PROW + x0];
                    float2 a = *(const float2*)rp;
                    float2 c = *(const float2*)(rp + 2);
                    ld[ic][r][0] = a.x; ld[ic][r][1] = a.y;
                    ld[ic][r][2] = c.x; ld[ic][r][3] = c.y;
                }

        #pragma unroll
        for (int dy = 0; dy < 2; dy++) {
            if (dy == 1 && !y1v) break;
            #pragma unroll
            for (int dx = 0; dx < 2; dx++) {
                if (dx == 1 && !x1v) break;
                float v[27];
                #pragma unroll
                for (int ic = 0; ic < 3; ic++)
                    #pragma unroll
                    for (int ky = 0; ky < 3; ky++)
                        #pragma unroll
                        for (int kx = 0; kx < 3; kx++)
                            v[ic * 9 + ky * 3 + kx] = ld[ic][ky + dy][kx + dx];
                store_a_row(smc, qb_off, (y0 + dy) * 31 + (x0 + dx), v);
            }
        }
    }
    asm volatile("cp.async.wait_group 0;" ::: "memory");
    __syncthreads();

    // ========== conv1 per set (w1 fragments + b1 hoisted) ==========
    uint32_t bw[2][2][4];
    #pragma unroll
    for (int ks = 0; ks < 2; ks++)
        #pragma unroll
        for (int g = 0; g < 2; g++)
            ldsm_x4(smb + W1B_OFF + (g * 16 + b_row) * 80 + b_kh * 16 + ks * 32,
                    bw[ks][g][0], bw[ks][g][1], bw[ks][g][2], bw[ks][g][3]);
    float b1c0[4], b1c1[4];
    #pragma unroll
    for (int j = 0; j < 4; j++) {
        int c0 = j * 8 + 2 * (lid & 3);
        b1c0[j] = b1s[c0];
        b1c1[j] = b1s[c0 + 1];
    }

    #pragma unroll
    for (int s = 0; s < 2; s++) {
        const uint32_t qb_off = s ? QS_OFF : QG_OFF;
        const uint32_t qb = smb + qb_off;

        uint32_t qv[4][4][2];
        uint32_t qoff[4][2];
        bool     qok[4][2];
        #pragma unroll
        for (int t = 0; t < 4; t++) {
            const int r0 = wid * 64 + t * 16;
            const uint32_t row = (uint32_t)r0 + arow_lane;
            const uint32_t sw  = (row >> 1) & 3u;
            const uint32_t rb  = qb + row * 64;
            uint32_t a[2][4];
            #pragma unroll
            for (int ks = 0; ks < 2; ks++)
                ldsm_x4(rb + ((((uint32_t)ks << 1) | a_kh) ^ sw) * 16,
                        a[ks][0], a[ks][1], a[ks][2], a[ks][3]);
            float d[4][4];
            #pragma unroll
            for (int j = 0; j < 4; j++)
                #pragma unroll
                for (int q = 0; q < 4; q++) d[j][q] = 0.0f;
            #pragma unroll
            for (int ks = 0; ks < 2; ks++)
                #pragma unroll
                for (int g = 0; g < 2; g++) {
                    mma16816(d[2 * g],     a[ks][0], a[ks][1], a[ks][2], a[ks][3],
                             bw[ks][g][0], bw[ks][g][1]);
                    mma16816(d[2 * g + 1], a[ks][0], a[ks][1], a[ks][2], a[ks][3],
                             bw[ks][g][2], bw[ks][g][3]);
                }
            const int m_lo = r0 + (lid >> 2);
            const int m_hi = m_lo + 8;
            qok[t][0]  = (m_lo < 961);
            qok[t][1]  = (m_hi < 961);
            qoff[t][0] = qofft[m_lo];
            qoff[t][1] = qofft[m_hi];
            #pragma unroll
            for (int j = 0; j < 4; j++) {
                qv[t][j][0] = bfpack(fmaxf(d[j][0] + b1c0[j], 0.f),
                                     fmaxf(d[j][1] + b1c1[j], 0.f));
                qv[t][j][1] = bfpack(fmaxf(d[j][2] + b1c0[j], 0.f),
                                     fmaxf(d[j][3] + b1c1[j], 0.f));
            }
        }
        __syncthreads();   // all A reads of this buffer done

        // scatter conv1 output into swizzled quadrant layout
        {
            const uint32_t cb = (uint32_t)(lid & 3) * 4;
            #pragma unroll
            for (int t = 0; t < 4; t++)
                #pragma unroll
                for (int h = 0; h < 2; h++)
                    if (qok[t][h]) {
                        const uint32_t ro = qoff[t][h];
                        const uint32_t sw = (ro >> 7) & 3u;
                        char* base = smc + qb_off + ro + cb;
                        #pragma unroll
                        for (int j = 0; j < 4; j++)
                            *(uint32_t*)(base + ((uint32_t)(j ^ sw) * 16)) = qv[t][j][h];
                    }
        }
        // s=0: no barrier — scatter(QG) overlaps conv1 on QS
        if (s == 1) __syncthreads();
    }

    // ========== conv2: shared B fragments across both sets ==========
    float acc[2][2][4][4];
    #pragma unroll
    for (int s = 0; s < 2; s++)
        #pragma unroll
        for (int t = 0; t < 2; t++)
            #pragma unroll
            for (int j = 0; j < 4; j++)
                #pragma unroll
                for (int q = 0; q < 4; q++) acc[s][t][j][q] = 0.0f;

    const int mg = wid & 7;
    const int ng = wid >> 3;

    #pragma unroll
    for (int tap = 0; tap < 9; tap++) {
        const int ky = tap / 3, kx = tap - 3 * ky;
        const int quad = ((ky & 1) << 1) | (kx & 1);
        const int d0   = ((ky >> 1) << 4) + (kx >> 1);
        const uint32_t row0 = (uint32_t)(quad * 256 + mg * 32 + d0) + arow_lane;
        const uint32_t sw   = (row0 >> 1) & 3u;
        const uint32_t off0 = row0 * 64;
        const uint32_t b_base = smb + W2S_OFF +
            (uint32_t)(tap * 64 + ng * 32 + b_row) * 80 + b_kh * 16;

        #pragma unroll
        for (int ks = 0; ks < 2; ks++) {
            const uint32_t coff = ((((uint32_t)ks << 1) | a_kh) ^ sw) * 16;
            uint32_t b0[4], b1r[4];
            ldsm_x4(b_base + ks * 32, b0[0], b0[1], b0[2], b0[3]);
            ldsm_x4(b_base + 16 * 80 + ks * 32, b1r[0], b1r[1], b1r[2], b1r[3]);

            #pragma unroll
            for (int s = 0; s < 2; s++) {
                const uint32_t qb = smb + (s ? QS_OFF : QG_OFF);
                uint32_t a0[4], a1[4];
                ldsm_x4(qb + off0 + coff, a0[0], a0[1], a0[2], a0[3]);
                ldsm_x4(qb + off0 + 1024 + coff, a1[0], a1[1], a1[2], a1[3]);

                mma16816(acc[s][0][0], a0[0], a0[1], a0[2], a0[3], b0[0],  b0[1]);
                mma16816(acc[s][0][1], a0[0], a0[1], a0[2], a0[3], b0[2],  b0[3]);
                mma16816(acc[s][0][2], a0[0], a0[1], a0[2], a0[3], b1r[0], b1r[1]);
                mma16816(acc[s][0][3], a0[0], a0[1], a0[2], a0[3], b1r[2], b1r[3]);
                mma16816(acc[s][1][0], a1[0], a1[1], a1[2], a1[3], b0[0],  b0[1]);
                mma16816(acc[s][1][1], a1[0], a1[1], a1[2], a1[3], b0[2],  b0[3]);
                mma16816(acc[s][1][2], a1[0], a1[1], a1[2], a1[3], b1r[0], b1r[1]);
                mma16816(acc[s][1][3], a1[0], a1[1], a1[2], a1[3], b1r[2], b1r[3]);
            }
        }
    }

    // ========== fused epilogue: both sets -> part/part2, ONE barrier ==========
    {
        const bool hi_ok = ((lid >> 2) != 7);
        #pragma unroll
        for (int s = 0; s < 2; s++) {
            float* pp = s ? part2 : part;
            #pragma unroll
            for (int t = 0; t < 2; t++) {
                const int oy = 2 * mg + t;
                const bool oy_ok = (oy < C2H);
                #pragma unroll
                for (int j = 0; j < 4; j++) {
                    int c0 = ng * 32 + j * 8 + 2 * (lid & 3);
                    float bb0 = b2s[c0], bb1 = b2s[c0 + 1];
                    float sA = 0.0f, sB = 0.0f;
                    if (oy_ok) {
                        sA = fmaxf(acc[s][t][j][0] + bb0, 0.0f);
                        sB = fmaxf(acc[s][t][j][1] + bb1, 0.0f);
                        if (hi_ok) {
                            sA += fmaxf(acc[s][t][j][2] + bb0, 0.0f);
                            sB += fmaxf(acc[s][t][j][3] + bb1, 0.0f);
                        }
                    }
                    #pragma unroll
                    for (int msk = 4; msk <= 16; msk <<= 1) {
                        sA += __shfl_xor_sync(0xffffffffu, sA, msk);
                        sB += __shfl_xor_sync(0xffffffffu, sB, msk);
                    }
                    if (lid < 4) {
                        pp[oy * 64 + c0]     = sA;
                        pp[oy * 64 + c0 + 1] = sB;
                    }
                }
            }
        }
    }
    __syncthreads();

    // feature difference (same op order as before: scale each, then subtract)
    if (tid < C2) {
        float s0 = 0.0f, s1 = 0.0f;
        #pragma unroll
        for (int ww = 0; ww < 16; ww++) {
            s0 += part[ww * 64 + tid];
            s1 += part2[ww * 64 + tid];
        }
        feat[tid] = s0 * (1.0f / 225.0f) - s1 * (1.0f / 225.0f);
    }
    __syncthreads();

    // ========== pair loss: sum((wl @ d)^2), wl from global ==========
    {
        const int j   = tid >> 2;       // output 0..127
        const int seg = tid & 3;        // 16-wide K segment
        float y = 0.0f;
        const float* wr = &wl[j * C2 + seg * 16];
        const float* dd = &feat[seg * 16];
        #pragma unroll
        for (int i = 0; i < 16; i++) y += wr[i] * dd[i];
        y += __shfl_xor_sync(0xffffffffu, y, 1);
        y += __shfl_xor_sync(0xffffffffu, y, 2);
        if (seg == 0) red[j] = y * y;
    }
    __syncthreads();
    #pragma unroll
    for (int st = 64; st > 0; st >>= 1) {
        if (tid < st) red[tid] += red[tid + st];
        __syncthreads();
    }
    if (tid == 0) g_pairsum[m] = red[0];
}

// ---------------------------------------------------------------------------
// Kernel C: final deterministic reduction + mean.
// ---------------------------------------------------------------------------
__global__ void __launch_bounds__(256)
reduce_kernel(float* __restrict__ out)
{
    __shared__ float red[256];
    const int tid = threadIdx.x;
    float s = 0.0f;
    for (int i = tid; i < NPATCH; i += 256) s += g_pairsum[i];
    red[tid] = s;
    __syncthreads();
    #pragma unroll
    for (int st = 128; st > 0; st >>= 1) {
        if (tid < st) red[tid] += red[tid + st];
        __syncthreads();
    }
    if (tid == 0)
        out[0] = red[0] / (float)((size_t)NPATCH * OUTF);
}

// ---------------------------------------------------------------------------
extern "C" void kernel_launch(void* const* d_in, const int* in_sizes, int n_in,
                              void* d_out, int out_size)
{
    const float* img_g = (const float*)d_in[0];
    const float* img_s = (const float*)d_in[1];
    const float* kp_g  = (const float*)d_in[2];
    const float* kp_s  = (const float*)d_in[3];
    const float* w1    = (const float*)d_in[4];
    const float* b1    = (const float*)d_in[5];
    const float* w2    = (const float*)d_in[6];
    const float* b2    = (const float*)d_in[7];
    const float* wl    = (const float*)d_in[8];
    // d_in[9] = bl (cancels), d_in[10] = num_samples (fixed)

    cudaFuncSetAttribute(pair_cnn_kernel,
                         cudaFuncAttributeMaxDynamicSharedMemorySize, SMEM_BYTES);

    prep_kernel<<<32, 512>>>(w1, w2);
    pair_cnn_kernel<<<NPATCH, 512, SMEM_BYTES>>>(img_g, img_s, kp_g, kp_s,
                                                 b1, b2, wl);
    reduce_kernel<<<1, 256>>>((float*)d_out);
}

// round 16
// speedup vs baseline: 1.3070x; 1.1002x over previous
#include <cuda_runtime.h>
#include <cuda_bf16.h>
#include <cstdint>

// Fixed problem shapes
#define SIGMA   16
#define PATCH   33
#define HW      256
#define NPATCH  1024
#define C1      32
#define C1H     31
#define C2      64
#define C2H     15
#define OUTF    128

// smem byte layout
//  two quad/A buffers: 1024 rows x 64B, XOR-swizzled (chunk ^= (row>>1)&3)
#define QG_OFF     0
#define QS_OFF     65536
#define W2S_OFF    131072               // 9*64 rows x 80B = 46080
#define W1B_OFF    177152               // 2560
#define B1S_OFF    179712               // 128
#define B2S_OFF    179840               // 256
#define QOFFT_OFF  180096               // 4096 (aliased: part2 in epilogue)
#define PART_OFF   184192               // 4096 (also last-block partials)
#define FEAT_OFF   188288               // 512
#define RED_OFF    188800               // 512
#define SMEM_BYTES 189312

__device__ float g_pairsum[NPATCH];
__device__ unsigned int g_done_ctr = 0;
// pre-converted weight images (bf16) — written by prep_kernel
__device__ uint4 g_w2s4[2880];          // 46080 B
__device__ uint4 g_w1b4[160];           // 2560 B

__device__ __forceinline__ uint32_t smem_u32(const void* p) {
    uint32_t a;
    asm("{ .reg .u64 t; cvta.to.shared.u64 t, %1; cvt.u32.u64 %0, t; }" : "=r"(a) : "l"(p));
    return a;
}

__device__ __forceinline__ void ldsm_x4(uint32_t addr, uint32_t& r0, uint32_t& r1,
                                        uint32_t& r2, uint32_t& r3) {
    asm volatile("ldmatrix.sync.aligned.m8n8.x4.shared.b16 {%0,%1,%2,%3}, [%4];"
                 : "=r"(r0), "=r"(r1), "=r"(r2), "=r"(r3) : "r"(addr));
}

__device__ __forceinline__ void mma16816(float* d, uint32_t a0, uint32_t a1,
                                         uint32_t a2, uint32_t a3,
                                         uint32_t b0, uint32_t b1) {
    asm volatile("mma.sync.aligned.m16n8k16.row.col.f32.bf16.bf16.f32 "
                 "{%0,%1,%2,%3}, {%4,%5,%6,%7}, {%8,%9}, {%0,%1,%2,%3};"
                 : "+f"(d[0]), "+f"(d[1]), "+f"(d[2]), "+f"(d[3])
                 : "r"(a0), "r"(a1), "r"(a2), "r"(a3), "r"(b0), "r"(b1));
}

__device__ __forceinline__ uint32_t bfpack(float lo, float hi) {
    __nv_bfloat162 v = __floats2bfloat162_rn(lo, hi);
    return *(uint32_t*)&v;
}

__device__ __forceinline__ void cp_async16(uint32_t dst, const void* src) {
    asm volatile("cp.async.ca.shared.global [%0], [%1], 16;" :: "r"(dst), "l"(src));
}

// quadrant row byte-offset (row*64) for conv1-output pixel m = y*31+x
__device__ __forceinline__ uint32_t quad_row_off(int m) {
    int y = m / 31;
    int x = m - 31 * y;
    int row = ((((y & 1) << 1) | (x & 1)) << 8) + ((y >> 1) << 4) + (x >> 1);
    return (uint32_t)row * 64;
}

// pack 27-tap fp32 vector -> 64B bf16 A row, XOR chunk swizzle
__device__ __forceinline__ void store_a_row(char* smc, uint32_t bufoff, int mm,
                                            const float* v) {
    uint32_t r[16];
    #pragma unroll
    for (int i = 0; i < 13; i++) r[i] = bfpack(v[2 * i], v[2 * i + 1]);
    r[13] = bfpack(v[26], 0.f);
    r[14] = 0u; r[15] = 0u;
    uint32_t sw = ((uint32_t)mm >> 1) & 3u;
    uint4* dst = (uint4*)(smc + bufoff + (uint32_t)mm * 64);
    uint4 c0 = make_uint4(r[0], r[1], r[2], r[3]);
    uint4 c1 = make_uint4(r[4], r[5], r[6], r[7]);
    uint4 c2 = make_uint4(r[8], r[9], r[10], r[11]);
    uint4 c3 = make_uint4(r[12], r[13], r[14], r[15]);
    dst[0 ^ sw] = c0; dst[1 ^ sw] = c1; dst[2 ^ sw] = c2; dst[3 ^ sw] = c3;
}

// ---------------------------------------------------------------------------
// Prep kernel: convert w1/w2 into bf16 smem-image layouts once (32 blocks).
// ---------------------------------------------------------------------------
__global__ void __launch_bounds__(512)
prep_kernel(const float* __restrict__ w1, const float* __restrict__ w2)
{
    const int i = blockIdx.x * 512 + threadIdx.x;
    if (i < 11520) {
        int row = i / 20, c = i - row * 20;
        uint32_t val = 0u;
        if (c < 16) {
            int tap = row >> 6, oc = row & 63;
            int ky = tap / 3, kx = tap - 3 * ky;
            const float* ws = w2 + ((size_t)(oc * C1 + 2 * c) * 3 + ky) * 3 + kx;
            val = bfpack(ws[0], ws[9]);
        }
        ((uint32_t*)g_w2s4)[i] = val;
    }
    if (i < 640) {
        int oc = i / 20, c = i - oc * 20;
        uint32_t val = 0u;
        if (c < 16) {
            float lo = (2 * c     < 27) ? w1[oc * 27 + 2 * c]     : 0.f;
            float hi = (2 * c + 1 < 27) ? w1[oc * 27 + 2 * c + 1] : 0.f;
            val = bfpack(lo, hi);
        }
        ((uint32_t*)g_w1b4)[i] = val;
    }
}

// ---------------------------------------------------------------------------
// Kernel A: one block per PAIR (1024 x 512). im2col reads global directly;
// conv2 shares B fragments across sets; fused epilogue; last-block reduction.
// ---------------------------------------------------------------------------
__global__ void __launch_bounds__(512, 1)
pair_cnn_kernel(const float* __restrict__ img_g, const float* __restrict__ img_s,
                const float* __restrict__ kp_g,  const float* __restrict__ kp_s,
                const float* __restrict__ b1,    const float* __restrict__ b2,
                const float* __restrict__ wl,    float* __restrict__ out)
{
    extern __shared__ char smc[];
    float* b1s   = (float*)(smc + B1S_OFF);
    float* b2s   = (float*)(smc + B2S_OFF);
    float* part  = (float*)(smc + PART_OFF);
    float* part2 = (float*)(smc + QOFFT_OFF);   // alias (qofft dead by epilogue)
    float* feat  = (float*)(smc + FEAT_OFF);
    float* red   = (float*)(smc + RED_OFF);
    uint32_t* qofft = (uint32_t*)(smc + QOFFT_OFF);
    __shared__ bool is_last;
    const uint32_t smb = smem_u32(smc);

    const int m = blockIdx.x;      // pair index
    const int n = m >> 2;
    const int b = m & 3;

    const int tid = threadIdx.x;
    const int wid = tid >> 5;
    const int lid = tid & 31;

    // ---- async weight-image copies (overlap global-read im2col) ----
    #pragma unroll
    for (int i = 0; i < 6; i++) {
        int idx = tid + i * 512;
        if (idx < 2880)
            cp_async16(smb + W2S_OFF + idx * 16, &g_w2s4[idx]);
    }
    if (tid < 160)
        cp_async16(smb + W1B_OFF + tid * 16, &g_w1b4[tid]);
    asm volatile("cp.async.commit_group;" ::: "memory");

    // ---- keypoint windows, biases, qoff table ----
    int sxy[2][2];
    {
        float gx = kp_g[2 * n], gy = kp_g[2 * n + 1];
        float sx_ = kp_s[2 * n], sy_ = kp_s[2 * n + 1];
        sxy[0][0] = min(max((int)floorf(gx * (float)HW) - SIGMA, 0), HW - PATCH);
        sxy[0][1] = min(max((int)floorf(gy * (float)HW) - SIGMA, 0), HW - PATCH);
        sxy[1][0] = min(max((int)floorf(sx_ * (float)HW) - SIGMA, 0), HW - PATCH);
        sxy[1][1] = min(max((int)floorf(sy_ * (float)HW) - SIGMA, 0), HW - PATCH);
    }
    qofft[tid]       = quad_row_off(tid);
    qofft[tid + 512] = quad_row_off(tid + 512 < 961 ? tid + 512 : 960);
    if (tid < C1) b1s[tid] = b1[tid];
    else if (tid < C1 + C2) b2s[tid - C1] = b2[tid - C1];

    const uint32_t arow_lane = (uint32_t)(lid & 15);
    const uint32_t a_kh  = (uint32_t)(lid >> 4);
    const uint32_t b_row = (uint32_t)((lid & 7) + ((lid >> 4) << 3));
    const uint32_t b_kh  = (uint32_t)((lid >> 3) & 1);

    // ========== im2col DIRECT FROM GLOBAL: both sets concurrently ==========
    {
        const int s  = tid >> 8;           // 0: ground, 1: satellite
        const int tt = tid & 255;
        const float* img = s ? img_s : img_g;
        const uint32_t qb_off = s ? QS_OFF : QG_OFF;
        const int sx = sxy[s][0], sy = sxy[s][1];

        const int by = tt >> 4, bx = tt & 15;
        const int y0 = 2 * by, x0 = 2 * bx;
        const bool y1v = (y0 + 1 < C1H);
        const bool x1v = (x0 + 1 < C1H);

        float ld[3][4][4];
        #pragma unroll
        for (int ic = 0; ic < 3; ic++)
            #pragma unroll
            for (int r = 0; r < 4; r++)
                if (r < 3 || y1v) {
                    const float* rp =
                        &img[(((size_t)b * 3 + ic) * HW + (sy + y0 + r)) * HW
                             + (sx + x0)];
                    ld[ic][r][0] = rp[0];
                    ld[ic][r][1] = rp[1];
                    ld[ic][r][2] = rp[2];
                    ld[ic][r][3] = x1v ? rp[3] : 0.0f;   // avoid OOB at x edge
                }

        #pragma unroll
        for (int dy = 0; dy < 2; dy++) {
            if (dy == 1 && !y1v) break;
            #pragma unroll
            for (int dx = 0; dx < 2; dx++) {
                if (dx == 1 && !x1v) break;
                float v[27];
                #pragma unroll
                for (int ic = 0; ic < 3; ic++)
                    #pragma unroll
                    for (int ky = 0; ky < 3; ky++)
                        #pragma unroll
                        for (int kx = 0; kx < 3; kx++)
                            v[ic * 9 + ky * 3 + kx] = ld[ic][ky + dy][kx + dx];
                store_a_row(smc, qb_off, (y0 + dy) * 31 + (x0 + dx), v);
            }
        }
    }
    asm volatile("cp.async.wait_group 0;" ::: "memory");
    __syncthreads();

    // ========== conv1 per set (w1 fragments + b1 hoisted) ==========
    uint32_t bw[2][2][4];
    #pragma unroll
    for (int ks = 0; ks < 2; ks++)
        #pragma unroll
        for (int g = 0; g < 2; g++)
            ldsm_x4(smb + W1B_OFF + (g * 16 + b_row) * 80 + b_kh * 16 + ks * 32,
                    bw[ks][g][0], bw[ks][g][1], bw[ks][g][2], bw[ks][g][3]);
    float b1c0[4], b1c1[4];
    #pragma unroll
    for (int j = 0; j < 4; j++) {
        int c0 = j * 8 + 2 * (lid & 3);
        b1c0[j] = b1s[c0];
        b1c1[j] = b1s[c0 + 1];
    }

    #pragma unroll
    for (int s = 0; s < 2; s++) {
        const uint32_t qb_off = s ? QS_OFF : QG_OFF;
        const uint32_t qb = smb + qb_off;

        uint32_t qv[4][4][2];
        uint32_t qoff[4][2];
        bool     qok[4][2];
        #pragma unroll
        for (int t = 0; t < 4; t++) {
            const int r0 = wid * 64 + t * 16;
            const uint32_t row = (uint32_t)r0 + arow_lane;
            const uint32_t sw  = (row >> 1) & 3u;
            const uint32_t rb  = qb + row * 64;
            uint32_t a[2][4];
            #pragma unroll
            for (int ks = 0; ks < 2; ks++)
                ldsm_x4(rb + ((((uint32_t)ks << 1) | a_kh) ^ sw) * 16,
                        a[ks][0], a[ks][1], a[ks][2], a[ks][3]);
            float d[4][4];
            #pragma unroll
            for (int j = 0; j < 4; j++)
                #pragma unroll
                for (int q = 0; q < 4; q++) d[j][q] = 0.0f;
            #pragma unroll
            for (int ks = 0; ks < 2; ks++)
                #pragma unroll
                for (int g = 0; g < 2; g++) {
                    mma16816(d[2 * g],     a[ks][0], a[ks][1], a[ks][2], a[ks][3],
                             bw[ks][g][0], bw[ks][g][1]);
                    mma16816(d[2 * g + 1], a[ks][0], a[ks][1], a[ks][2], a[ks][3],
                             bw[ks][g][2], bw[ks][g][3]);
                }
            const int m_lo = r0 + (lid >> 2);
            const int m_hi = m_lo + 8;
            qok[t][0]  = (m_lo < 961);
            qok[t][1]  = (m_hi < 961);
            qoff[t][0] = qofft[m_lo];
            qoff[t][1] = qofft[m_hi];
            #pragma unroll
            for (int j = 0; j < 4; j++) {
                qv[t][j][0] = bfpack(fmaxf(d[j][0] + b1c0[j], 0.f),
                                     fmaxf(d[j][1] + b1c1[j], 0.f));
                qv[t][j][1] = bfpack(fmaxf(d[j][2] + b1c0[j], 0.f),
                                     fmaxf(d[j][3] + b1c1[j], 0.f));
            }
        }
        __syncthreads();   // all A reads of this buffer done

        // scatter conv1 output into swizzled quadrant layout
        {
            const uint32_t cb = (uint32_t)(lid & 3) * 4;
            #pragma unroll
            for (int t = 0; t < 4; t++)
                #pragma unroll
                for (int h = 0; h < 2; h++)
                    if (qok[t][h]) {
                        const uint32_t ro = qoff[t][h];
                        const uint32_t sw = (ro >> 7) & 3u;
                        char* base = smc + qb_off + ro + cb;
                        #pragma unroll
                        for (int j = 0; j < 4; j++)
                            *(uint32_t*)(base + ((uint32_t)(j ^ sw) * 16)) = qv[t][j][h];
                    }
        }
        // s=0: no barrier — scatter(QG) overlaps conv1 on QS
        if (s == 1) __syncthreads();
    }

    // ========== conv2: shared B fragments across both sets ==========
    float acc[2][2][4][4];
    #pragma unroll
    for (int s = 0; s < 2; s++)
        #pragma unroll
        for (int t = 0; t < 2; t++)
            #pragma unroll
            for (int j = 0; j < 4; j++)
                #pragma unroll
                for (int q = 0; q < 4; q++) acc[s][t][j][q] = 0.0f;

    const int mg = wid & 7;
    const int ng = wid >> 3;

    #pragma unroll
    for (int tap = 0; tap < 9; tap++) {
        const int ky = tap / 3, kx = tap - 3 * ky;
        const int quad = ((ky & 1) << 1) | (kx & 1);
        const int d0   = ((ky >> 1) << 4) + (kx >> 1);
        const uint32_t row0 = (uint32_t)(quad * 256 + mg * 32 + d0) + arow_lane;
        const uint32_t sw   = (row0 >> 1) & 3u;
        const uint32_t off0 = row0 * 64;
        const uint32_t b_base = smb + W2S_OFF +
            (uint32_t)(tap * 64 + ng * 32 + b_row) * 80 + b_kh * 16;

        #pragma unroll
        for (int ks = 0; ks < 2; ks++) {
            const uint32_t coff = ((((uint32_t)ks << 1) | a_kh) ^ sw) * 16;
            uint32_t b0[4], b1r[4];
            ldsm_x4(b_base + ks * 32, b0[0], b0[1], b0[2], b0[3]);
            ldsm_x4(b_base + 16 * 80 + ks * 32, b1r[0], b1r[1], b1r[2], b1r[3]);

            #pragma unroll
            for (int s = 0; s < 2; s++) {
                const uint32_t qb = smb + (s ? QS_OFF : QG_OFF);
                uint32_t a0[4], a1[4];
                ldsm_x4(qb + off0 + coff, a0[0], a0[1], a0[2], a0[3]);
                ldsm_x4(qb + off0 + 1024 + coff, a1[0], a1[1], a1[2], a1[3]);

                mma16816(acc[s][0][0], a0[0], a0[1], a0[2], a0[3], b0[0],  b0[1]);
                mma16816(acc[s][0][1], a0[0], a0[1], a0[2], a0[3], b0[2],  b0[3]);
                mma16816(acc[s][0][2], a0[0], a0[1], a0[2], a0[3], b1r[0], b1r[1]);
                mma16816(acc[s][0][3], a0[0], a0[1], a0[2], a0[3], b1r[2], b1r[3]);
                mma16816(acc[s][1][0], a1[0], a1[1], a1[2], a1[3], b0[0],  b0[1]);
                mma16816(acc[s][1][1], a1[0], a1[1], a1[2], a1[3], b0[2],  b0[3]);
                mma16816(acc[s][1][2], a1[0], a1[1], a1[2], a1[3], b1r[0], b1r[1]);
                mma16816(acc[s][1][3], a1[0], a1[1], a1[2], a1[3], b1r[2], b1r[3]);
            }
        }
    }

    // ========== fused epilogue: both sets -> part/part2, ONE barrier ==========
    {
        const bool hi_ok = ((lid >> 2) != 7);
        #pragma unroll
        for (int s = 0; s < 2; s++) {
            float* pp = s ? part2 : part;
            #pragma unroll
            for (int t = 0; t < 2; t++) {
                const int oy = 2 * mg + t;
                const bool oy_ok = (oy < C2H);
                #pragma unroll
                for (int j = 0; j < 4; j++) {
                    int c0 = ng * 32 + j * 8 + 2 * (lid & 3);
                    float bb0 = b2s[c0], bb1 = b2s[c0 + 1];
                    float sA = 0.0f, sB = 0.0f;
                    if (oy_ok) {
                        sA = fmaxf(acc[s][t][j][0] + bb0, 0.0f);
                        sB = fmaxf(acc[s][t][j][1] + bb1, 0.0f);
                        if (hi_ok) {
                            sA += fmaxf(acc[s][t][j][2] + bb0, 0.0f);
                            sB += fmaxf(acc[s][t][j][3] + bb1, 0.0f);
                        }
                    }
                    #pragma unroll
                    for (int msk = 4; msk <= 16; msk <<= 1) {
                        sA += __shfl_xor_sync(0xffffffffu, sA, msk);
                        sB += __shfl_xor_sync(0xffffffffu, sB, msk);
                    }
                    if (lid < 4) {
                        pp[oy * 64 + c0]     = sA;
                        pp[oy * 64 + c0 + 1] = sB;
                    }
                }
            }
        }
    }
    __syncthreads();

    // feature difference (scale each, then subtract)
    if (tid < C2) {
        float s0 = 0.0f, s1 = 0.0f;
        #pragma unroll
        for (int ww = 0; ww < 16; ww++) {
            s0 += part[ww * 64 + tid];
            s1 += part2[ww * 64 + tid];
        }
        feat[tid] = s0 * (1.0f / 225.0f) - s1 * (1.0f / 225.0f);
    }
    __syncthreads();

    // ========== pair loss: sum((wl @ d)^2), wl from global ==========
    {
        const int j   = tid >> 2;       // output 0..127
        const int seg = tid & 3;        // 16-wide K segment
        float y = 0.0f;
        const float* wr = &wl[j * C2 + seg * 16];
        const float* dd = &feat[seg * 16];
        #pragma unroll
        for (int i = 0; i < 16; i++) y += wr[i] * dd[i];
        y += __shfl_xor_sync(0xffffffffu, y, 1);
        y += __shfl_xor_sync(0xffffffffu, y, 2);
        if (seg == 0) red[j] = y * y;
    }
    __syncthreads();
    #pragma unroll
    for (int st = 64; st > 0; st >>= 1) {
        if (tid < st) red[tid] += red[tid + st];
        __syncthreads();
    }

    // ========== last-block final reduction (threadfence pattern) ==========
    if (tid == 0) {
        g_pairsum[m] = red[0];
        __threadfence();
        unsigned int t = atomicAdd(&g_done_ctr, 1u);
        is_last = (t == NPATCH - 1);
    }
    __syncthreads();

    if (is_last) {
        __threadfence();
        float s = g_pairsum[tid] + g_pairsum[tid + 512];
        part[tid] = s;
        __syncthreads();
        #pragma unroll
        for (int st = 256; st > 0; st >>= 1) {
            if (tid < st) part[tid] += part[tid + st];
            __syncthreads();
        }
        if (tid == 0) {
            out[0] = part[0] / (float)((size_t)NPATCH * OUTF);
            g_done_ctr = 0;      // reset for next graph replay
        }
    }
}

// ---------------------------------------------------------------------------
extern "C" void kernel_launch(void* const* d_in, const int* in_sizes, int n_in,
                              void* d_out, int out_size)
{
    const float* img_g = (const float*)d_in[0];
    const float* img_s = (const float*)d_in[1];
    const float* kp_g  = (const float*)d_in[2];
    const float* kp_s  = (const float*)d_in[3];
    const float* w1    = (const float*)d_in[4];
    const float* b1    = (const float*)d_in[5];
    const float* w2    = (const float*)d_in[6];
    const float* b2    = (const float*)d_in[7];
    const float* wl    = (const float*)d_in[8];
    // d_in[9] = bl (cancels), d_in[10] = num_samples (fixed)

    cudaFuncSetAttribute(pair_cnn_kernel,
                         cudaFuncAttributeMaxDynamicSharedMemorySize, SMEM_BYTES);

    prep_kernel<<<32, 512>>>(w1, w2);
    pair_cnn_kernel<<<NPATCH, 512, SMEM_BYTES>>>(img_g, img_s, kp_g, kp_s,
                                                 b1, b2, wl, (float*)d_out);
}